// round 1
// baseline (speedup 1.0000x reference)
#include <cuda_runtime.h>

#define BB  2
#define SS  2048
#define DMM 1024
#define HH  16
#define DHH 64
#define BH  (BB*HH)   // 32

// ---------------- scratch (device globals; no runtime allocation) ----------------
__device__ float g_q[BB*HH*SS*DHH];      // 4M floats
__device__ float g_k[BB*HH*SS*DHH];
__device__ float g_v[BB*HH*SS*DHH];
__device__ float g_att[BB*SS*DMM];       // attention output, [B,S,DA] head-interleaved
__device__ float g_erT[DHH*SS];          // Er[0:2048] transposed: [64][2048]
__device__ float g_rel[134217728];       // [BH][S][S] = 512MB, R[q,r] = Q[q]·Er[r]

// ---------------- Er transpose ----------------
__global__ void k_transpose_er(const float* __restrict__ Er) {
    int idx = blockIdx.x * 256 + threadIdx.x;   // 0 .. 64*2048-1
    int d = idx >> 11, r = idx & 2047;
    g_erT[idx] = Er[r * 64 + d];
    (void)d;
}

// ---------------- fused QKV projection GEMM ----------------
// M=4096, K=1024. N-tiles 0..23: tiles 0-7 -> Q, 8-15 -> K, 16-23 -> V.
__global__ __launch_bounds__(256) void k_qkv(
    const float* __restrict__ x,
    const float* __restrict__ Wq, const float* __restrict__ Wk, const float* __restrict__ Wv,
    const float* __restrict__ bq, const float* __restrict__ bk, const float* __restrict__ bv)
{
    __shared__ float As[8][132];
    __shared__ float Bs[8][128];
    int bx = blockIdx.x, by = blockIdx.y;
    int which = bx >> 3;
    const float* W    = (which == 0) ? Wq : ((which == 1) ? Wk : Wv);
    const float* bias = (which == 0) ? bq : ((which == 1) ? bk : bv);
    float*       dst  = (which == 0) ? g_q : ((which == 1) ? g_k : g_v);
    int nb = (bx & 7) * 128;          // column offset inside the selected weight
    int bm = by * 128;

    int tid = threadIdx.x;
    int tx = tid & 15, ty = tid >> 4;
    int a_row = tid >> 1, a_col = (tid & 1) * 4;
    int b_row = tid >> 5, b_col = (tid & 31) * 4;

    float acc[8][8];
#pragma unroll
    for (int i = 0; i < 8; i++)
#pragma unroll
        for (int j = 0; j < 8; j++) acc[i][j] = 0.f;

    const float* Aptr = x + (size_t)(bm + a_row) * DMM + a_col;
    const float* Bptr = W + (size_t)b_row * DMM + nb + b_col;

    for (int k0 = 0; k0 < DMM; k0 += 8) {
        float4 av = *(const float4*)(Aptr + k0);
        As[a_col + 0][a_row] = av.x;
        As[a_col + 1][a_row] = av.y;
        As[a_col + 2][a_row] = av.z;
        As[a_col + 3][a_row] = av.w;
        *(float4*)&Bs[b_row][b_col] = *(const float4*)(Bptr + (size_t)k0 * DMM);
        __syncthreads();
#pragma unroll
        for (int kk = 0; kk < 8; kk++) {
            float ar[8], br[8];
            *(float4*)&ar[0] = *(float4*)&As[kk][ty * 8];
            *(float4*)&ar[4] = *(float4*)&As[kk][ty * 8 + 4];
            *(float4*)&br[0] = *(float4*)&Bs[kk][tx * 8];
            *(float4*)&br[4] = *(float4*)&Bs[kk][tx * 8 + 4];
#pragma unroll
            for (int i = 0; i < 8; i++)
#pragma unroll
                for (int j = 0; j < 8; j++) acc[i][j] += ar[i] * br[j];
        }
        __syncthreads();
    }

    // epilogue: head-major scatter, contiguous 8 in d per row -> two float4 stores
#pragma unroll
    for (int i = 0; i < 8; i++) {
        int m = bm + ty * 8 + i;
        int b = m >> 11, s = m & 2047;
        int nloc = nb + tx * 8;
        int h = nloc >> 6, d = nloc & 63;
        float4 o0, o1;
        o0.x = acc[i][0] + bias[nloc + 0];
        o0.y = acc[i][1] + bias[nloc + 1];
        o0.z = acc[i][2] + bias[nloc + 2];
        o0.w = acc[i][3] + bias[nloc + 3];
        o1.x = acc[i][4] + bias[nloc + 4];
        o1.y = acc[i][5] + bias[nloc + 5];
        o1.z = acc[i][6] + bias[nloc + 6];
        o1.w = acc[i][7] + bias[nloc + 7];
        float* p = dst + (((size_t)b * HH + h) * SS + s) * DHH + d;
        *(float4*)p = o0;
        *(float4*)(p + 4) = o1;
    }
}

// ---------------- REL GEMM: R[bh][q][r] = Q[bh][q]·Er[r], triangular tile skip ----------------
__global__ __launch_bounds__(256) void k_rel()
{
    int bh = blockIdx.z;
    int r0 = blockIdx.x * 128, q0 = blockIdx.y * 128;
    if (q0 + r0 < 1793) return;   // tile never consumed under the causal band

    __shared__ float As[8][132];
    __shared__ float Bs[8][128];
    const float* A = g_q + (size_t)bh * SS * DHH;

    int tid = threadIdx.x;
    int tx = tid & 15, ty = tid >> 4;
    int a_row = tid >> 1, a_col = (tid & 1) * 4;
    int b_row = tid >> 5, b_col = (tid & 31) * 4;

    float acc[8][8];
#pragma unroll
    for (int i = 0; i < 8; i++)
#pragma unroll
        for (int j = 0; j < 8; j++) acc[i][j] = 0.f;

    for (int k0 = 0; k0 < DHH; k0 += 8) {
        float4 av = *(const float4*)&A[(size_t)(q0 + a_row) * DHH + k0 + a_col];
        As[a_col + 0][a_row] = av.x;
        As[a_col + 1][a_row] = av.y;
        As[a_col + 2][a_row] = av.z;
        As[a_col + 3][a_row] = av.w;
        *(float4*)&Bs[b_row][b_col] = *(const float4*)&g_erT[(size_t)(k0 + b_row) * SS + r0 + b_col];
        __syncthreads();
#pragma unroll
        for (int kk = 0; kk < 8; kk++) {
            float ar[8], br[8];
            *(float4*)&ar[0] = *(float4*)&As[kk][ty * 8];
            *(float4*)&ar[4] = *(float4*)&As[kk][ty * 8 + 4];
            *(float4*)&br[0] = *(float4*)&Bs[kk][tx * 8];
            *(float4*)&br[4] = *(float4*)&Bs[kk][tx * 8 + 4];
#pragma unroll
            for (int i = 0; i < 8; i++)
#pragma unroll
                for (int j = 0; j < 8; j++) acc[i][j] += ar[i] * br[j];
        }
        __syncthreads();
    }

    float* C = g_rel + (size_t)bh * SS * SS;
#pragma unroll
    for (int i = 0; i < 8; i++) {
        size_t row = (size_t)(q0 + ty * 8 + i) * SS + r0 + tx * 8;
        float4 o0, o1;
        o0.x = acc[i][0]; o0.y = acc[i][1]; o0.z = acc[i][2]; o0.w = acc[i][3];
        o1.x = acc[i][4]; o1.y = acc[i][5]; o1.z = acc[i][6]; o1.w = acc[i][7];
        *(float4*)&C[row]     = o0;
        *(float4*)&C[row + 4] = o1;
    }
}

// ---------------- flash attention with fused relative bias + causal mask ----------------
// Block: 128 queries of one (b,h). 256 threads as 16(ty:q) x 16(tx:k|d).
// smem: QsT[64][132] | KsT[64][132] | Vs[128][68] | Ps[128][132]  = 169984 B
#define ATTN_SMEM_FLOATS (64*132 + 64*132 + 128*68 + 128*132)

__global__ __launch_bounds__(256) void k_attn()
{
    extern __shared__ float smf[];
    float* QsT = smf;                 // [d][q]  stride 132
    float* KsT = smf + 64 * 132;      // [d][k]  stride 132
    float* Vs  = smf + 2 * 64 * 132;  // [k][d]  stride 68
    float* Ps  = Vs + 128 * 68;       // [q][k]  stride 132

    int bh = blockIdx.y;
    int qt = gridDim.x - 1 - blockIdx.x;   // heavy (diagonal-rich) tiles first
    int q0 = qt * 128;
    const float* Q  = g_q + (size_t)bh * SS * DHH;
    const float* Kp = g_k + (size_t)bh * SS * DHH;
    const float* Vp = g_v + (size_t)bh * SS * DHH;
    const float* R  = g_rel + (size_t)bh * SS * SS;

    int tid = threadIdx.x;
    int tx = tid & 15, ty = tid >> 4;

    // load Q tile transposed
#pragma unroll
    for (int i = 0; i < 32; i++) {
        int idx = i * 256 + tid;
        int qi = idx >> 6, d = idx & 63;
        QsT[d * 132 + qi] = Q[(size_t)(q0 + qi) * DHH + d];
    }

    float m_i[8], l_i[8], o[8][4];
#pragma unroll
    for (int i = 0; i < 8; i++) {
        m_i[i] = -3.0e38f;
        l_i[i] = 0.f;
#pragma unroll
        for (int dd = 0; dd < 4; dd++) o[i][dd] = 0.f;
    }

    int ntiles = qt + 1;
    for (int t = 0; t < ntiles; t++) {
        int k0 = t * 128;
        __syncthreads();   // prior P·V done: KsT/Vs/Ps reusable
#pragma unroll
        for (int i = 0; i < 32; i++) {
            int idx = i * 256 + tid;
            int ki = idx >> 6, d = idx & 63;
            KsT[d * 132 + ki] = Kp[(size_t)(k0 + ki) * DHH + d];
            Vs[ki * 68 + d]   = Vp[(size_t)(k0 + ki) * DHH + d];
        }
        __syncthreads();

        // ---- scores S = Q·K^T ----
        float s[8][8];
#pragma unroll
        for (int i = 0; i < 8; i++)
#pragma unroll
            for (int j = 0; j < 8; j++) s[i][j] = 0.f;

#pragma unroll 8
        for (int d = 0; d < 64; d++) {
            float qr[8], kr[8];
            *(float4*)&qr[0] = *(float4*)&QsT[d * 132 + ty * 8];
            *(float4*)&qr[4] = *(float4*)&QsT[d * 132 + ty * 8 + 4];
            *(float4*)&kr[0] = *(float4*)&KsT[d * 132 + tx * 8];
            *(float4*)&kr[4] = *(float4*)&KsT[d * 132 + tx * 8 + 4];
#pragma unroll
            for (int i = 0; i < 8; i++)
#pragma unroll
                for (int j = 0; j < 8; j++) s[i][j] += qr[i] * kr[j];
        }

        // ---- + relative bias, scale, causal mask ----
#pragma unroll
        for (int i = 0; i < 8; i++) {
            int q = q0 + ty * 8 + i;
            const float* Rrow = R + (size_t)q * SS + (SS - 1 - q) + k0 + tx * 8;
#pragma unroll
            for (int j = 0; j < 8; j++) {
                float v = (s[i][j] + Rrow[j]) * 0.125f;   // 1/sqrt(64)
                int k = k0 + tx * 8 + j;
                s[i][j] = (k <= q) ? v : -1.0e30f;
            }
        }

        // ---- online softmax (row reductions over the 16 tx lanes) ----
#pragma unroll
        for (int i = 0; i < 8; i++) {
            float mt = s[i][0];
#pragma unroll
            for (int j = 1; j < 8; j++) mt = fmaxf(mt, s[i][j]);
#pragma unroll
            for (int off = 8; off > 0; off >>= 1)
                mt = fmaxf(mt, __shfl_xor_sync(0xffffffffu, mt, off));
            float mnew = fmaxf(m_i[i], mt);
            float corr = __expf(m_i[i] - mnew);
            m_i[i] = mnew;
            float rs = 0.f;
#pragma unroll
            for (int j = 0; j < 8; j++) {
                float p = __expf(s[i][j] - mnew);
                s[i][j] = p;
                rs += p;
            }
#pragma unroll
            for (int off = 8; off > 0; off >>= 1)
                rs += __shfl_xor_sync(0xffffffffu, rs, off);
            l_i[i] = l_i[i] * corr + rs;
#pragma unroll
            for (int dd = 0; dd < 4; dd++) o[i][dd] *= corr;
        }

        // ---- stage P, then O += P·V ----
#pragma unroll
        for (int i = 0; i < 8; i++) {
            float4 p0, p1;
            p0.x = s[i][0]; p0.y = s[i][1]; p0.z = s[i][2]; p0.w = s[i][3];
            p1.x = s[i][4]; p1.y = s[i][5]; p1.z = s[i][6]; p1.w = s[i][7];
            *(float4*)&Ps[(ty * 8 + i) * 132 + tx * 8]     = p0;
            *(float4*)&Ps[(ty * 8 + i) * 132 + tx * 8 + 4] = p1;
        }
        __syncthreads();

#pragma unroll 4
        for (int k = 0; k < 128; k++) {
            float4 vv = *(float4*)&Vs[k * 68 + tx * 4];
            float pr[8];
#pragma unroll
            for (int i = 0; i < 8; i++) pr[i] = Ps[(ty * 8 + i) * 132 + k];
#pragma unroll
            for (int i = 0; i < 8; i++) {
                o[i][0] += pr[i] * vv.x;
                o[i][1] += pr[i] * vv.y;
                o[i][2] += pr[i] * vv.z;
                o[i][3] += pr[i] * vv.w;
            }
        }
    }

    // ---- normalize + write [B,S,DA] head-interleaved ----
    int b = bh >> 4, h = bh & 15;
#pragma unroll
    for (int i = 0; i < 8; i++) {
        float inv = 1.0f / l_i[i];
        float4 ov;
        ov.x = o[i][0] * inv;
        ov.y = o[i][1] * inv;
        ov.z = o[i][2] * inv;
        ov.w = o[i][3] * inv;
        int q = q0 + ty * 8 + i;
        *(float4*)&g_att[((size_t)(b * SS + q)) * DMM + h * 64 + tx * 4] = ov;
    }
}

// ---------------- output projection: out = g_att @ Wo + bo ----------------
__global__ __launch_bounds__(256) void k_out(
    const float* __restrict__ Wo, const float* __restrict__ bo, float* __restrict__ out)
{
    __shared__ float As[8][132];
    __shared__ float Bs[8][128];
    int bn = blockIdx.x * 128, bm = blockIdx.y * 128;

    int tid = threadIdx.x;
    int tx = tid & 15, ty = tid >> 4;
    int a_row = tid >> 1, a_col = (tid & 1) * 4;
    int b_row = tid >> 5, b_col = (tid & 31) * 4;

    float acc[8][8];
#pragma unroll
    for (int i = 0; i < 8; i++)
#pragma unroll
        for (int j = 0; j < 8; j++) acc[i][j] = 0.f;

    const float* Aptr = g_att + (size_t)(bm + a_row) * DMM + a_col;
    const float* Bptr = Wo + (size_t)b_row * DMM + bn + b_col;

    for (int k0 = 0; k0 < DMM; k0 += 8) {
        float4 av = *(const float4*)(Aptr + k0);
        As[a_col + 0][a_row] = av.x;
        As[a_col + 1][a_row] = av.y;
        As[a_col + 2][a_row] = av.z;
        As[a_col + 3][a_row] = av.w;
        *(float4*)&Bs[b_row][b_col] = *(const float4*)(Bptr + (size_t)k0 * DMM);
        __syncthreads();
#pragma unroll
        for (int kk = 0; kk < 8; kk++) {
            float ar[8], br[8];
            *(float4*)&ar[0] = *(float4*)&As[kk][ty * 8];
            *(float4*)&ar[4] = *(float4*)&As[kk][ty * 8 + 4];
            *(float4*)&br[0] = *(float4*)&Bs[kk][tx * 8];
            *(float4*)&br[4] = *(float4*)&Bs[kk][tx * 8 + 4];
#pragma unroll
            for (int i = 0; i < 8; i++)
#pragma unroll
                for (int j = 0; j < 8; j++) acc[i][j] += ar[i] * br[j];
        }
        __syncthreads();
    }

#pragma unroll
    for (int i = 0; i < 8; i++) {
        int m = bm + ty * 8 + i;
        int n = bn + tx * 8;
        float4 o0, o1;
        o0.x = acc[i][0] + bo[n + 0];
        o0.y = acc[i][1] + bo[n + 1];
        o0.z = acc[i][2] + bo[n + 2];
        o0.w = acc[i][3] + bo[n + 3];
        o1.x = acc[i][4] + bo[n + 4];
        o1.y = acc[i][5] + bo[n + 5];
        o1.z = acc[i][6] + bo[n + 6];
        o1.w = acc[i][7] + bo[n + 7];
        float* p = out + (size_t)m * DMM + n;
        *(float4*)p = o0;
        *(float4*)(p + 4) = o1;
    }
}

// ---------------- launch ----------------
extern "C" void kernel_launch(void* const* d_in, const int* in_sizes, int n_in,
                              void* d_out, int out_size)
{
    const float* x  = (const float*)d_in[0];
    const float* Wq = (const float*)d_in[1];
    const float* bq = (const float*)d_in[2];
    const float* Wk = (const float*)d_in[3];
    const float* bk = (const float*)d_in[4];
    const float* Wv = (const float*)d_in[5];
    const float* bv = (const float*)d_in[6];
    const float* Wo = (const float*)d_in[7];
    const float* bo = (const float*)d_in[8];
    const float* Er = (const float*)d_in[9];
    float* out = (float*)d_out;

    cudaFuncSetAttribute((const void*)k_attn,
                         cudaFuncAttributeMaxDynamicSharedMemorySize,
                         ATTN_SMEM_FLOATS * (int)sizeof(float));

    k_transpose_er<<<512, 256>>>(Er);
    k_qkv<<<dim3(24, 32), 256>>>(x, Wq, Wk, Wv, bq, bk, bv);
    k_rel<<<dim3(16, 16, 32), 256>>>();
    k_attn<<<dim3(16, 32), 256, ATTN_SMEM_FLOATS * sizeof(float)>>>();
    k_out<<<dim3(8, 32), 256>>>(Wo, bo, out);
}

// round 2
// speedup vs baseline: 1.0320x; 1.0320x over previous
#include <cuda_runtime.h>

#define BB  2
#define SS  2048
#define DMM 1024
#define HH  16
#define DHH 64
#define BH  (BB*HH)   // 32

// ---------------- scratch (device globals; no runtime allocation) ----------------
__device__ float g_q[BB*HH*SS*DHH];
__device__ float g_k[BB*HH*SS*DHH];
__device__ float g_v[BB*HH*SS*DHH];
__device__ float g_att[BB*SS*DMM];
__device__ float g_erT[DHH*SS];          // Er[0:2048] transposed: [64][2048]
__device__ float g_rel[134217728];       // [BH][S][S], R[q,r] = Q[q]·Er[r]

// ---------------- Er transpose ----------------
__global__ void k_transpose_er(const float* __restrict__ Er) {
    int idx = blockIdx.x * 256 + threadIdx.x;   // 0 .. 64*2048-1
    int r = idx & 2047;
    int d = idx >> 11;
    g_erT[idx] = Er[r * 64 + d];
}

// ---------------- fused QKV projection GEMM (Bk=16, double-buffered, 2 CTA/SM) ----------------
__global__ __launch_bounds__(256, 2) void k_qkv(
    const float* __restrict__ x,
    const float* __restrict__ Wq, const float* __restrict__ Wk, const float* __restrict__ Wv,
    const float* __restrict__ bq, const float* __restrict__ bk, const float* __restrict__ bv)
{
    __shared__ float As[2][16][132];
    __shared__ float Bs[2][16][128];
    int bx = blockIdx.x, by = blockIdx.y;
    int which = bx >> 3;
    const float* W    = (which == 0) ? Wq : ((which == 1) ? Wk : Wv);
    const float* bias = (which == 0) ? bq : ((which == 1) ? bk : bv);
    float*       dst  = (which == 0) ? g_q : ((which == 1) ? g_k : g_v);
    int nb = (bx & 7) * 128;
    int bm = by * 128;

    int tid = threadIdx.x;
    int tx = tid & 15, ty = tid >> 4;
    int arow = tid >> 2, ac4 = tid & 3;      // A: 64 rows per pass, 2 passes (+64)
    int brow = tid >> 5, bc4 = tid & 31;     // B: 8 rows per pass, 2 passes (+8)

    const float* Ap = x + (size_t)(bm + arow) * DMM + ac4 * 4;
    const float* Bp = W + (size_t)brow * DMM + nb + bc4 * 4;

    float4 a0, a1, b0, b1;
    // prologue: tile 0
    a0 = *(const float4*)(Ap);
    a1 = *(const float4*)(Ap + (size_t)64 * DMM);
    b0 = *(const float4*)(Bp);
    b1 = *(const float4*)(Bp + (size_t)8 * DMM);
    As[0][ac4*4+0][arow] = a0.x; As[0][ac4*4+1][arow] = a0.y;
    As[0][ac4*4+2][arow] = a0.z; As[0][ac4*4+3][arow] = a0.w;
    As[0][ac4*4+0][arow+64] = a1.x; As[0][ac4*4+1][arow+64] = a1.y;
    As[0][ac4*4+2][arow+64] = a1.z; As[0][ac4*4+3][arow+64] = a1.w;
    *(float4*)&Bs[0][brow][bc4*4]   = b0;
    *(float4*)&Bs[0][brow+8][bc4*4] = b1;
    __syncthreads();

    float acc[8][8];
#pragma unroll
    for (int i = 0; i < 8; i++)
#pragma unroll
        for (int j = 0; j < 8; j++) acc[i][j] = 0.f;

    for (int it = 0; it < 64; it++) {
        int cur = it & 1;
        bool more = (it < 63);
        if (more) {
            const float* Ap2 = Ap + (it + 1) * 16;
            const float* Bp2 = Bp + (size_t)(it + 1) * 16 * DMM;
            a0 = *(const float4*)(Ap2);
            a1 = *(const float4*)(Ap2 + (size_t)64 * DMM);
            b0 = *(const float4*)(Bp2);
            b1 = *(const float4*)(Bp2 + (size_t)8 * DMM);
        }
#pragma unroll
        for (int kk = 0; kk < 16; kk++) {
            float ar[8], br[8];
            *(float4*)&ar[0] = *(float4*)&As[cur][kk][ty * 8];
            *(float4*)&ar[4] = *(float4*)&As[cur][kk][ty * 8 + 4];
            *(float4*)&br[0] = *(float4*)&Bs[cur][kk][tx * 8];
            *(float4*)&br[4] = *(float4*)&Bs[cur][kk][tx * 8 + 4];
#pragma unroll
            for (int i = 0; i < 8; i++)
#pragma unroll
                for (int j = 0; j < 8; j++) acc[i][j] += ar[i] * br[j];
        }
        if (more) {
            int nxt = cur ^ 1;
            As[nxt][ac4*4+0][arow] = a0.x; As[nxt][ac4*4+1][arow] = a0.y;
            As[nxt][ac4*4+2][arow] = a0.z; As[nxt][ac4*4+3][arow] = a0.w;
            As[nxt][ac4*4+0][arow+64] = a1.x; As[nxt][ac4*4+1][arow+64] = a1.y;
            As[nxt][ac4*4+2][arow+64] = a1.z; As[nxt][ac4*4+3][arow+64] = a1.w;
            *(float4*)&Bs[nxt][brow][bc4*4]   = b0;
            *(float4*)&Bs[nxt][brow+8][bc4*4] = b1;
            __syncthreads();
        }
    }

    // epilogue: head-major scatter
#pragma unroll
    for (int i = 0; i < 8; i++) {
        int m = bm + ty * 8 + i;
        int b = m >> 11, s = m & 2047;
        int nloc = nb + tx * 8;
        int h = nloc >> 6, d = nloc & 63;
        float4 o0, o1;
        o0.x = acc[i][0] + bias[nloc + 0];
        o0.y = acc[i][1] + bias[nloc + 1];
        o0.z = acc[i][2] + bias[nloc + 2];
        o0.w = acc[i][3] + bias[nloc + 3];
        o1.x = acc[i][4] + bias[nloc + 4];
        o1.y = acc[i][5] + bias[nloc + 5];
        o1.z = acc[i][6] + bias[nloc + 6];
        o1.w = acc[i][7] + bias[nloc + 7];
        float* p = dst + (((size_t)b * HH + h) * SS + s) * DHH + d;
        *(float4*)p = o0;
        *(float4*)(p + 4) = o1;
    }
}

// ---------------- REL GEMM with triangular tile skip ----------------
__global__ __launch_bounds__(256, 2) void k_rel()
{
    int bh = blockIdx.z;
    int r0 = blockIdx.x * 128, q0 = blockIdx.y * 128;
    if (q0 + r0 < 1793) return;

    __shared__ float As[8][132];
    __shared__ float Bs[8][128];
    const float* A = g_q + (size_t)bh * SS * DHH;

    int tid = threadIdx.x;
    int tx = tid & 15, ty = tid >> 4;
    int a_row = tid >> 1, a_col = (tid & 1) * 4;
    int b_row = tid >> 5, b_col = (tid & 31) * 4;

    float acc[8][8];
#pragma unroll
    for (int i = 0; i < 8; i++)
#pragma unroll
        for (int j = 0; j < 8; j++) acc[i][j] = 0.f;

    for (int k0 = 0; k0 < DHH; k0 += 8) {
        float4 av = *(const float4*)&A[(size_t)(q0 + a_row) * DHH + k0 + a_col];
        As[a_col + 0][a_row] = av.x;
        As[a_col + 1][a_row] = av.y;
        As[a_col + 2][a_row] = av.z;
        As[a_col + 3][a_row] = av.w;
        *(float4*)&Bs[b_row][b_col] = *(const float4*)&g_erT[(size_t)(k0 + b_row) * SS + r0 + b_col];
        __syncthreads();
#pragma unroll
        for (int kk = 0; kk < 8; kk++) {
            float ar[8], br[8];
            *(float4*)&ar[0] = *(float4*)&As[kk][ty * 8];
            *(float4*)&ar[4] = *(float4*)&As[kk][ty * 8 + 4];
            *(float4*)&br[0] = *(float4*)&Bs[kk][tx * 8];
            *(float4*)&br[4] = *(float4*)&Bs[kk][tx * 8 + 4];
#pragma unroll
            for (int i = 0; i < 8; i++)
#pragma unroll
                for (int j = 0; j < 8; j++) acc[i][j] += ar[i] * br[j];
        }
        __syncthreads();
    }

    float* C = g_rel + (size_t)bh * SS * SS;
#pragma unroll
    for (int i = 0; i < 8; i++) {
        size_t row = (size_t)(q0 + ty * 8 + i) * SS + r0 + tx * 8;
        float4 o0, o1;
        o0.x = acc[i][0]; o0.y = acc[i][1]; o0.z = acc[i][2]; o0.w = acc[i][3];
        o1.x = acc[i][4]; o1.y = acc[i][5]; o1.z = acc[i][6]; o1.w = acc[i][7];
        *(float4*)&C[row]     = o0;
        *(float4*)&C[row + 4] = o1;
    }
}

// ---------------- flash attention, 512 threads, Bq=128 x Bk=256 ----------------
// smem: QsT[64][132] | KsT[64][260] | Vs[256][68] | Ps[128][68] = 51200 floats = 200KB
#define ATTN_SMEM_FLOATS (64*132 + 64*260 + 256*68 + 128*68)

__global__ __launch_bounds__(512) void k_attn()
{
    extern __shared__ float smf[];
    float* QsT = smf;                       // [d][q]  stride 132
    float* KsT = smf + 64 * 132;            // [d][k]  stride 260
    float* Vs  = KsT + 64 * 260;            // [k][d]  stride 68
    float* Ps  = Vs + 256 * 68;             // [q][kc] stride 68 (64-wide chunk)

    int bh = blockIdx.y;
    int qt = (int)gridDim.x - 1 - (int)blockIdx.x;   // heavy tiles first
    int q0 = qt * 128;
    const float* Q  = g_q + (size_t)bh * SS * DHH;
    const float* Kp = g_k + (size_t)bh * SS * DHH;
    const float* Vp = g_v + (size_t)bh * SS * DHH;
    const float* R  = g_rel + (size_t)bh * SS * SS;

    int tid = threadIdx.x;
    int tx = tid & 31, ty = tid >> 5;

    // load Q tile transposed
#pragma unroll
    for (int i = 0; i < 16; i++) {
        int idx = i * 512 + tid;
        int qi = idx >> 6, d = idx & 63;
        QsT[d * 132 + qi] = Q[(size_t)(q0 + qi) * DHH + d];
    }

    float m_i[8], l_i[8], o[8][2];
#pragma unroll
    for (int i = 0; i < 8; i++) {
        m_i[i] = -3.0e38f;
        l_i[i] = 0.f;
        o[i][0] = 0.f; o[i][1] = 0.f;
    }

    int qmax = q0 + 127;
    int nt = (qt >> 1) + 1;
    for (int t = 0; t < nt; t++) {
        int k0 = t * 256;
        __syncthreads();
#pragma unroll
        for (int i = 0; i < 32; i++) {
            int idx = i * 512 + tid;
            int ki = idx >> 6, d = idx & 63;
            KsT[d * 260 + ki] = Kp[(size_t)(k0 + ki) * DHH + d];
        }
#pragma unroll
        for (int i = 0; i < 8; i++) {
            int idx = i * 512 + tid;
            int ki = idx >> 4, c4 = idx & 15;
            *(float4*)&Vs[ki * 68 + c4 * 4] = *(const float4*)&Vp[(size_t)(k0 + ki) * DHH + c4 * 4];
        }
        __syncthreads();

        // ---- scores S = Q·K^T over 256-wide k tile ----
        float s[8][8];
#pragma unroll
        for (int i = 0; i < 8; i++)
#pragma unroll
            for (int j = 0; j < 8; j++) s[i][j] = 0.f;

#pragma unroll 8
        for (int d = 0; d < 64; d++) {
            float qr[8], kr[8];
            *(float4*)&qr[0] = *(float4*)&QsT[d * 132 + ty * 8];
            *(float4*)&qr[4] = *(float4*)&QsT[d * 132 + ty * 8 + 4];
            *(float4*)&kr[0] = *(float4*)&KsT[d * 260 + tx * 8];
            *(float4*)&kr[4] = *(float4*)&KsT[d * 260 + tx * 8 + 4];
#pragma unroll
            for (int i = 0; i < 8; i++)
#pragma unroll
                for (int j = 0; j < 8; j++) s[i][j] += qr[i] * kr[j];
        }

        // ---- + rel bias, scale, causal mask, online softmax (full-warp rows) ----
#pragma unroll
        for (int i = 0; i < 8; i++) {
            int q = q0 + ty * 8 + i;
            const float* Rrow = R + (size_t)q * SS + (SS - 1 - q) + k0 + tx * 8;
#pragma unroll
            for (int j = 0; j < 8; j++) {
                float v = (s[i][j] + Rrow[j]) * 0.125f;
                s[i][j] = ((k0 + tx * 8 + j) <= q) ? v : -1.0e30f;
            }
            float mt = s[i][0];
#pragma unroll
            for (int j = 1; j < 8; j++) mt = fmaxf(mt, s[i][j]);
#pragma unroll
            for (int off = 16; off > 0; off >>= 1)
                mt = fmaxf(mt, __shfl_xor_sync(0xffffffffu, mt, off));
            float mnew = fmaxf(m_i[i], mt);
            float corr = __expf(m_i[i] - mnew);
            m_i[i] = mnew;
            float rs = 0.f;
#pragma unroll
            for (int j = 0; j < 8; j++) {
                float p = __expf(s[i][j] - mnew);
                s[i][j] = p;
                rs += p;
            }
#pragma unroll
            for (int off = 16; off > 0; off >>= 1)
                rs += __shfl_xor_sync(0xffffffffu, rs, off);
            l_i[i] = l_i[i] * corr + rs;
            o[i][0] *= corr;
            o[i][1] *= corr;
        }

        // ---- P·V in 64-wide k chunks ----
#pragma unroll
        for (int c = 0; c < 4; c++) {
            if (k0 + c * 64 > qmax) break;
            __syncthreads();
            if ((tx >> 3) == c) {
#pragma unroll
                for (int i = 0; i < 8; i++) {
                    float* p = &Ps[(ty * 8 + i) * 68 + (tx & 7) * 8];
                    *(float4*)p       = make_float4(s[i][0], s[i][1], s[i][2], s[i][3]);
                    *(float4*)(p + 4) = make_float4(s[i][4], s[i][5], s[i][6], s[i][7]);
                }
            }
            __syncthreads();
#pragma unroll 4
            for (int k4 = 0; k4 < 16; k4++) {
                int kb = c * 64 + k4 * 4;
                float2 vv0 = *(float2*)&Vs[(kb + 0) * 68 + tx * 2];
                float2 vv1 = *(float2*)&Vs[(kb + 1) * 68 + tx * 2];
                float2 vv2 = *(float2*)&Vs[(kb + 2) * 68 + tx * 2];
                float2 vv3 = *(float2*)&Vs[(kb + 3) * 68 + tx * 2];
#pragma unroll
                for (int i = 0; i < 8; i++) {
                    float4 pr = *(float4*)&Ps[(ty * 8 + i) * 68 + k4 * 4];
                    o[i][0] += pr.x * vv0.x + pr.y * vv1.x + pr.z * vv2.x + pr.w * vv3.x;
                    o[i][1] += pr.x * vv0.y + pr.y * vv1.y + pr.z * vv2.y + pr.w * vv3.y;
                }
            }
        }
    }

    // ---- normalize + write head-interleaved [B,S,DA] ----
    int b = bh >> 4, h = bh & 15;
#pragma unroll
    for (int i = 0; i < 8; i++) {
        float inv = 1.0f / l_i[i];
        float2 ov;
        ov.x = o[i][0] * inv;
        ov.y = o[i][1] * inv;
        int q = q0 + ty * 8 + i;
        *(float2*)&g_att[((size_t)(b * SS + q)) * DMM + h * 64 + tx * 2] = ov;
    }
}

// ---------------- output projection (same pipelined GEMM) ----------------
__global__ __launch_bounds__(256, 2) void k_out(
    const float* __restrict__ Wo, const float* __restrict__ bo, float* __restrict__ out)
{
    __shared__ float As[2][16][132];
    __shared__ float Bs[2][16][128];
    int bn = blockIdx.x * 128, bm = blockIdx.y * 128;

    int tid = threadIdx.x;
    int tx = tid & 15, ty = tid >> 4;
    int arow = tid >> 2, ac4 = tid & 3;
    int brow = tid >> 5, bc4 = tid & 31;

    const float* Ap = g_att + (size_t)(bm + arow) * DMM + ac4 * 4;
    const float* Bp = Wo + (size_t)brow * DMM + bn + bc4 * 4;

    float4 a0, a1, b0, b1;
    a0 = *(const float4*)(Ap);
    a1 = *(const float4*)(Ap + (size_t)64 * DMM);
    b0 = *(const float4*)(Bp);
    b1 = *(const float4*)(Bp + (size_t)8 * DMM);
    As[0][ac4*4+0][arow] = a0.x; As[0][ac4*4+1][arow] = a0.y;
    As[0][ac4*4+2][arow] = a0.z; As[0][ac4*4+3][arow] = a0.w;
    As[0][ac4*4+0][arow+64] = a1.x; As[0][ac4*4+1][arow+64] = a1.y;
    As[0][ac4*4+2][arow+64] = a1.z; As[0][ac4*4+3][arow+64] = a1.w;
    *(float4*)&Bs[0][brow][bc4*4]   = b0;
    *(float4*)&Bs[0][brow+8][bc4*4] = b1;
    __syncthreads();

    float acc[8][8];
#pragma unroll
    for (int i = 0; i < 8; i++)
#pragma unroll
        for (int j = 0; j < 8; j++) acc[i][j] = 0.f;

    for (int it = 0; it < 64; it++) {
        int cur = it & 1;
        bool more = (it < 63);
        if (more) {
            const float* Ap2 = Ap + (it + 1) * 16;
            const float* Bp2 = Bp + (size_t)(it + 1) * 16 * DMM;
            a0 = *(const float4*)(Ap2);
            a1 = *(const float4*)(Ap2 + (size_t)64 * DMM);
            b0 = *(const float4*)(Bp2);
            b1 = *(const float4*)(Bp2 + (size_t)8 * DMM);
        }
#pragma unroll
        for (int kk = 0; kk < 16; kk++) {
            float ar[8], br[8];
            *(float4*)&ar[0] = *(float4*)&As[cur][kk][ty * 8];
            *(float4*)&ar[4] = *(float4*)&As[cur][kk][ty * 8 + 4];
            *(float4*)&br[0] = *(float4*)&Bs[cur][kk][tx * 8];
            *(float4*)&br[4] = *(float4*)&Bs[cur][kk][tx * 8 + 4];
#pragma unroll
            for (int i = 0; i < 8; i++)
#pragma unroll
                for (int j = 0; j < 8; j++) acc[i][j] += ar[i] * br[j];
        }
        if (more) {
            int nxt = cur ^ 1;
            As[nxt][ac4*4+0][arow] = a0.x; As[nxt][ac4*4+1][arow] = a0.y;
            As[nxt][ac4*4+2][arow] = a0.z; As[nxt][ac4*4+3][arow] = a0.w;
            As[nxt][ac4*4+0][arow+64] = a1.x; As[nxt][ac4*4+1][arow+64] = a1.y;
            As[nxt][ac4*4+2][arow+64] = a1.z; As[nxt][ac4*4+3][arow+64] = a1.w;
            *(float4*)&Bs[nxt][brow][bc4*4]   = b0;
            *(float4*)&Bs[nxt][brow+8][bc4*4] = b1;
            __syncthreads();
        }
    }

#pragma unroll
    for (int i = 0; i < 8; i++) {
        int m = bm + ty * 8 + i;
        int n = bn + tx * 8;
        float4 o0, o1;
        o0.x = acc[i][0] + bo[n + 0];
        o0.y = acc[i][1] + bo[n + 1];
        o0.z = acc[i][2] + bo[n + 2];
        o0.w = acc[i][3] + bo[n + 3];
        o1.x = acc[i][4] + bo[n + 4];
        o1.y = acc[i][5] + bo[n + 5];
        o1.z = acc[i][6] + bo[n + 6];
        o1.w = acc[i][7] + bo[n + 7];
        float* p = out + (size_t)m * DMM + n;
        *(float4*)p = o0;
        *(float4*)(p + 4) = o1;
    }
}

// ---------------- launch ----------------
extern "C" void kernel_launch(void* const* d_in, const int* in_sizes, int n_in,
                              void* d_out, int out_size)
{
    const float* x  = (const float*)d_in[0];
    const float* Wq = (const float*)d_in[1];
    const float* bq = (const float*)d_in[2];
    const float* Wk = (const float*)d_in[3];
    const float* bk = (const float*)d_in[4];
    const float* Wv = (const float*)d_in[5];
    const float* bv = (const float*)d_in[6];
    const float* Wo = (const float*)d_in[7];
    const float* bo = (const float*)d_in[8];
    const float* Er = (const float*)d_in[9];
    float* out = (float*)d_out;

    cudaFuncSetAttribute((const void*)k_attn,
                         cudaFuncAttributeMaxDynamicSharedMemorySize,
                         ATTN_SMEM_FLOATS * (int)sizeof(float));

    k_transpose_er<<<512, 256>>>(Er);
    k_qkv<<<dim3(24, 32), 256>>>(x, Wq, Wk, Wv, bq, bk, bv);
    k_rel<<<dim3(16, 16, 32), 256>>>();
    k_attn<<<dim3(16, 32), 512, ATTN_SMEM_FLOATS * sizeof(float)>>>();
    k_out<<<dim3(8, 32), 256>>>(Wo, bo, out);
}

// round 3
// speedup vs baseline: 1.6820x; 1.6298x over previous
#include <cuda_runtime.h>
#include <cstdint>

#define BB  2
#define SS  2048
#define DMM 1024
#define HH  16
#define DHH 64
#define BH  (BB*HH)   // 32

// ---------------- scratch (device globals; no runtime allocation) ----------------
__device__ float g_q[BB*HH*SS*DHH];
__device__ float g_k[BB*HH*SS*DHH];
__device__ float g_v[BB*HH*SS*DHH];
__device__ float g_att[BB*SS*DMM];
__device__ float g_erT[DHH*SS];          // Er[0:2048] transposed: [64][2048]
__device__ float g_rel[134217728];       // [BH][S][S], R[q,r] = Q[q]·Er[r]

// ---------------- helpers ----------------
__device__ __forceinline__ uint32_t f2tf(float f) {
    uint32_t u;
    asm("cvt.rna.tf32.f32 %0, %1;" : "=r"(u) : "f"(f));
    return u;
}

__device__ __forceinline__ void mma_tf32(float* c, const uint32_t* a, const uint32_t* b) {
    asm("mma.sync.aligned.m16n8k8.row.col.f32.tf32.tf32.f32 "
        "{%0,%1,%2,%3},{%4,%5,%6,%7},{%8,%9},{%0,%1,%2,%3};"
        : "+f"(c[0]), "+f"(c[1]), "+f"(c[2]), "+f"(c[3])
        : "r"(a[0]), "r"(a[1]), "r"(a[2]), "r"(a[3]), "r"(b[0]), "r"(b[1]));
}

// ---------------- Er transpose ----------------
__global__ void k_transpose_er(const float* __restrict__ Er) {
    int idx = blockIdx.x * 256 + threadIdx.x;   // 0 .. 64*2048-1
    int r = idx & 2047;
    int d = idx >> 11;
    g_erT[idx] = Er[r * 64 + d];
}

// ---------------- fused QKV projection, TF32 tensor-core GEMM ----------------
// CTA tile 128x128, 8 warps (2m x 4n), warp tile 64x32, mma m16n8k8, kb=16 double-buffered.
#define AS_STRIDE 20
#define BS_STRIDE 136
__global__ __launch_bounds__(256, 2) void k_qkv(
    const float* __restrict__ x,
    const float* __restrict__ Wq, const float* __restrict__ Wk, const float* __restrict__ Wv,
    const float* __restrict__ bq, const float* __restrict__ bk, const float* __restrict__ bv)
{
    __shared__ uint32_t As[2][128 * AS_STRIDE];
    __shared__ uint32_t Bs[2][16 * BS_STRIDE];

    int bx = blockIdx.x, by = blockIdx.y;
    int which = bx >> 3;
    const float* W    = (which == 0) ? Wq : ((which == 1) ? Wk : Wv);
    const float* bias = (which == 0) ? bq : ((which == 1) ? bk : bv);
    float*       dst  = (which == 0) ? g_q : ((which == 1) ? g_k : g_v);
    int nb = (bx & 7) * 128;
    int bm = by * 128;

    int tid = threadIdx.x;
    int lane = tid & 31, wid = tid >> 5;
    int warpM = wid >> 2, warpN = wid & 3;
    int g = lane >> 2, tg = lane & 3;
    int arow = tid >> 2, ac = (tid & 3) * 4;
    int brow = tid >> 5, bc = (tid & 31) * 4;

    const float* Ap = x + (size_t)(bm + arow) * DMM + ac;
    const float* Bp = W + (size_t)brow * DMM + nb + bc;

    // prologue: stage k-tile 0
    {
        float4 a0 = *(const float4*)Ap;
        float4 a1 = *(const float4*)(Ap + (size_t)64 * DMM);
        float4 b0 = *(const float4*)Bp;
        float4 b1 = *(const float4*)(Bp + (size_t)8 * DMM);
        uint32_t* p;
        p = &As[0][arow * AS_STRIDE + ac];
        p[0] = f2tf(a0.x); p[1] = f2tf(a0.y); p[2] = f2tf(a0.z); p[3] = f2tf(a0.w);
        p = &As[0][(arow + 64) * AS_STRIDE + ac];
        p[0] = f2tf(a1.x); p[1] = f2tf(a1.y); p[2] = f2tf(a1.z); p[3] = f2tf(a1.w);
        p = &Bs[0][brow * BS_STRIDE + bc];
        p[0] = f2tf(b0.x); p[1] = f2tf(b0.y); p[2] = f2tf(b0.z); p[3] = f2tf(b0.w);
        p = &Bs[0][(brow + 8) * BS_STRIDE + bc];
        p[0] = f2tf(b1.x); p[1] = f2tf(b1.y); p[2] = f2tf(b1.z); p[3] = f2tf(b1.w);
    }
    __syncthreads();

    float c[4][4][4];
#pragma unroll
    for (int mt = 0; mt < 4; mt++)
#pragma unroll
        for (int nt = 0; nt < 4; nt++)
#pragma unroll
            for (int r = 0; r < 4; r++) c[mt][nt][r] = 0.f;

    for (int it = 0; it < 64; it++) {
        int cur = it & 1;
        float4 a0, a1, b0, b1;
        bool more = (it < 63);
        if (more) {
            const float* Ap2 = Ap + (it + 1) * 16;
            const float* Bp2 = Bp + (size_t)(it + 1) * 16 * DMM;
            a0 = *(const float4*)Ap2;
            a1 = *(const float4*)(Ap2 + (size_t)64 * DMM);
            b0 = *(const float4*)Bp2;
            b1 = *(const float4*)(Bp2 + (size_t)8 * DMM);
        }
#pragma unroll
        for (int ks2 = 0; ks2 < 2; ks2++) {
            int ks = ks2 * 8;
            uint32_t af[4][4], bf[4][2];
#pragma unroll
            for (int mt = 0; mt < 4; mt++) {
                int rb = warpM * 64 + mt * 16;
                af[mt][0] = As[cur][(rb + g)     * AS_STRIDE + ks + tg];
                af[mt][1] = As[cur][(rb + g + 8) * AS_STRIDE + ks + tg];
                af[mt][2] = As[cur][(rb + g)     * AS_STRIDE + ks + tg + 4];
                af[mt][3] = As[cur][(rb + g + 8) * AS_STRIDE + ks + tg + 4];
            }
#pragma unroll
            for (int nt = 0; nt < 4; nt++) {
                int cb = warpN * 32 + nt * 8;
                bf[nt][0] = Bs[cur][(ks + tg)     * BS_STRIDE + cb + g];
                bf[nt][1] = Bs[cur][(ks + tg + 4) * BS_STRIDE + cb + g];
            }
#pragma unroll
            for (int mt = 0; mt < 4; mt++)
#pragma unroll
                for (int nt = 0; nt < 4; nt++)
                    mma_tf32(c[mt][nt], af[mt], bf[nt]);
        }
        if (more) {
            int nxt = cur ^ 1;
            uint32_t* p;
            p = &As[nxt][arow * AS_STRIDE + ac];
            p[0] = f2tf(a0.x); p[1] = f2tf(a0.y); p[2] = f2tf(a0.z); p[3] = f2tf(a0.w);
            p = &As[nxt][(arow + 64) * AS_STRIDE + ac];
            p[0] = f2tf(a1.x); p[1] = f2tf(a1.y); p[2] = f2tf(a1.z); p[3] = f2tf(a1.w);
            p = &Bs[nxt][brow * BS_STRIDE + bc];
            p[0] = f2tf(b0.x); p[1] = f2tf(b0.y); p[2] = f2tf(b0.z); p[3] = f2tf(b0.w);
            p = &Bs[nxt][(brow + 8) * BS_STRIDE + bc];
            p[0] = f2tf(b1.x); p[1] = f2tf(b1.y); p[2] = f2tf(b1.z); p[3] = f2tf(b1.w);
            __syncthreads();
        }
    }

    // epilogue: +bias, head-major scatter (cols 2tg,2tg+1 are d-contiguous -> float2)
#pragma unroll
    for (int mt = 0; mt < 4; mt++) {
#pragma unroll
        for (int nt = 0; nt < 4; nt++) {
            int nloc = nb + warpN * 32 + nt * 8 + 2 * tg;
            int h = nloc >> 6, d = nloc & 63;
            float b0v = bias[nloc], b1v = bias[nloc + 1];
            int m0 = bm + warpM * 64 + mt * 16 + g;
            int m1 = m0 + 8;
            {
                int b = m0 >> 11, s = m0 & 2047;
                float2 o; o.x = c[mt][nt][0] + b0v; o.y = c[mt][nt][1] + b1v;
                *(float2*)&dst[(((size_t)b * HH + h) * SS + s) * DHH + d] = o;
            }
            {
                int b = m1 >> 11, s = m1 & 2047;
                float2 o; o.x = c[mt][nt][2] + b0v; o.y = c[mt][nt][3] + b1v;
                *(float2*)&dst[(((size_t)b * HH + h) * SS + s) * DHH + d] = o;
            }
        }
    }
}

// ---------------- REL GEMM (TF32), triangular tile skip ----------------
__global__ __launch_bounds__(256, 2) void k_rel()
{
    int bh = blockIdx.z;
    int r0 = blockIdx.x * 128, q0 = blockIdx.y * 128;
    if (q0 + r0 < 1793) return;

    __shared__ uint32_t As[2][128 * AS_STRIDE];
    __shared__ uint32_t Bs[2][16 * BS_STRIDE];

    const float* A = g_q + (size_t)bh * SS * DHH;

    int tid = threadIdx.x;
    int lane = tid & 31, wid = tid >> 5;
    int warpM = wid >> 2, warpN = wid & 3;
    int g = lane >> 2, tg = lane & 3;
    int arow = tid >> 2, ac = (tid & 3) * 4;
    int brow = tid >> 5, bc = (tid & 31) * 4;

    const float* Ap = A + (size_t)(q0 + arow) * DHH + ac;
    const float* Bp = g_erT + (size_t)brow * SS + r0 + bc;

    {
        float4 a0 = *(const float4*)Ap;
        float4 a1 = *(const float4*)(Ap + (size_t)64 * DHH);
        float4 b0 = *(const float4*)Bp;
        float4 b1 = *(const float4*)(Bp + (size_t)8 * SS);
        uint32_t* p;
        p = &As[0][arow * AS_STRIDE + ac];
        p[0] = f2tf(a0.x); p[1] = f2tf(a0.y); p[2] = f2tf(a0.z); p[3] = f2tf(a0.w);
        p = &As[0][(arow + 64) * AS_STRIDE + ac];
        p[0] = f2tf(a1.x); p[1] = f2tf(a1.y); p[2] = f2tf(a1.z); p[3] = f2tf(a1.w);
        p = &Bs[0][brow * BS_STRIDE + bc];
        p[0] = f2tf(b0.x); p[1] = f2tf(b0.y); p[2] = f2tf(b0.z); p[3] = f2tf(b0.w);
        p = &Bs[0][(brow + 8) * BS_STRIDE + bc];
        p[0] = f2tf(b1.x); p[1] = f2tf(b1.y); p[2] = f2tf(b1.z); p[3] = f2tf(b1.w);
    }
    __syncthreads();

    float c[4][4][4];
#pragma unroll
    for (int mt = 0; mt < 4; mt++)
#pragma unroll
        for (int nt = 0; nt < 4; nt++)
#pragma unroll
            for (int r = 0; r < 4; r++) c[mt][nt][r] = 0.f;

    for (int it = 0; it < 4; it++) {
        int cur = it & 1;
        float4 a0, a1, b0, b1;
        bool more = (it < 3);
        if (more) {
            const float* Ap2 = Ap + (it + 1) * 16;
            const float* Bp2 = Bp + (size_t)(it + 1) * 16 * SS;
            a0 = *(const float4*)Ap2;
            a1 = *(const float4*)(Ap2 + (size_t)64 * DHH);
            b0 = *(const float4*)Bp2;
            b1 = *(const float4*)(Bp2 + (size_t)8 * SS);
        }
#pragma unroll
        for (int ks2 = 0; ks2 < 2; ks2++) {
            int ks = ks2 * 8;
            uint32_t af[4][4], bf[4][2];
#pragma unroll
            for (int mt = 0; mt < 4; mt++) {
                int rb = warpM * 64 + mt * 16;
                af[mt][0] = As[cur][(rb + g)     * AS_STRIDE + ks + tg];
                af[mt][1] = As[cur][(rb + g + 8) * AS_STRIDE + ks + tg];
                af[mt][2] = As[cur][(rb + g)     * AS_STRIDE + ks + tg + 4];
                af[mt][3] = As[cur][(rb + g + 8) * AS_STRIDE + ks + tg + 4];
            }
#pragma unroll
            for (int nt = 0; nt < 4; nt++) {
                int cb = warpN * 32 + nt * 8;
                bf[nt][0] = Bs[cur][(ks + tg)     * BS_STRIDE + cb + g];
                bf[nt][1] = Bs[cur][(ks + tg + 4) * BS_STRIDE + cb + g];
            }
#pragma unroll
            for (int mt = 0; mt < 4; mt++)
#pragma unroll
                for (int nt = 0; nt < 4; nt++)
                    mma_tf32(c[mt][nt], af[mt], bf[nt]);
        }
        if (more) {
            int nxt = cur ^ 1;
            uint32_t* p;
            p = &As[nxt][arow * AS_STRIDE + ac];
            p[0] = f2tf(a0.x); p[1] = f2tf(a0.y); p[2] = f2tf(a0.z); p[3] = f2tf(a0.w);
            p = &As[nxt][(arow + 64) * AS_STRIDE + ac];
            p[0] = f2tf(a1.x); p[1] = f2tf(a1.y); p[2] = f2tf(a1.z); p[3] = f2tf(a1.w);
            p = &Bs[nxt][brow * BS_STRIDE + bc];
            p[0] = f2tf(b0.x); p[1] = f2tf(b0.y); p[2] = f2tf(b0.z); p[3] = f2tf(b0.w);
            p = &Bs[nxt][(brow + 8) * BS_STRIDE + bc];
            p[0] = f2tf(b1.x); p[1] = f2tf(b1.y); p[2] = f2tf(b1.z); p[3] = f2tf(b1.w);
            __syncthreads();
        }
    }

    float* C = g_rel + (size_t)bh * SS * SS;
#pragma unroll
    for (int mt = 0; mt < 4; mt++) {
#pragma unroll
        for (int nt = 0; nt < 4; nt++) {
            int col = r0 + warpN * 32 + nt * 8 + 2 * tg;
            int m0 = q0 + warpM * 64 + mt * 16 + g;
            float2 o0; o0.x = c[mt][nt][0]; o0.y = c[mt][nt][1];
            float2 o1; o1.x = c[mt][nt][2]; o1.y = c[mt][nt][3];
            *(float2*)&C[(size_t)m0 * SS + col]       = o0;
            *(float2*)&C[(size_t)(m0 + 8) * SS + col] = o1;
        }
    }
}

// ---------------- flash attention (R1 shape: 256 thr, Bq=128 x Bk=128) ----------------
#define ATTN_SMEM_FLOATS (64*132 + 64*132 + 128*68 + 128*132)

__global__ __launch_bounds__(256) void k_attn()
{
    extern __shared__ float smf[];
    float* QsT = smf;                 // [d][q]  stride 132
    float* KsT = smf + 64 * 132;      // [d][k]  stride 132
    float* Vs  = smf + 2 * 64 * 132;  // [k][d]  stride 68
    float* Ps  = Vs + 128 * 68;       // [q][k]  stride 132

    int bh = blockIdx.y;
    int qt = (int)gridDim.x - 1 - (int)blockIdx.x;   // heavy tiles first
    int q0 = qt * 128;
    const float* Q  = g_q + (size_t)bh * SS * DHH;
    const float* Kp = g_k + (size_t)bh * SS * DHH;
    const float* Vp = g_v + (size_t)bh * SS * DHH;
    const float* R  = g_rel + (size_t)bh * SS * SS;

    int tid = threadIdx.x;
    int tx = tid & 15, ty = tid >> 4;

#pragma unroll
    for (int i = 0; i < 32; i++) {
        int idx = i * 256 + tid;
        int qi = idx >> 6, d = idx & 63;
        QsT[d * 132 + qi] = Q[(size_t)(q0 + qi) * DHH + d];
    }

    float m_i[8], l_i[8], o[8][4];
#pragma unroll
    for (int i = 0; i < 8; i++) {
        m_i[i] = -3.0e38f;
        l_i[i] = 0.f;
#pragma unroll
        for (int dd = 0; dd < 4; dd++) o[i][dd] = 0.f;
    }

    int ntiles = qt + 1;
    for (int t = 0; t < ntiles; t++) {
        int k0 = t * 128;
        __syncthreads();
#pragma unroll
        for (int i = 0; i < 32; i++) {
            int idx = i * 256 + tid;
            int ki = idx >> 6, d = idx & 63;
            KsT[d * 132 + ki] = Kp[(size_t)(k0 + ki) * DHH + d];
            Vs[ki * 68 + d]   = Vp[(size_t)(k0 + ki) * DHH + d];
        }
        __syncthreads();

        float s[8][8];
#pragma unroll
        for (int i = 0; i < 8; i++)
#pragma unroll
            for (int j = 0; j < 8; j++) s[i][j] = 0.f;

#pragma unroll 8
        for (int d = 0; d < 64; d++) {
            float qr[8], kr[8];
            *(float4*)&qr[0] = *(float4*)&QsT[d * 132 + ty * 8];
            *(float4*)&qr[4] = *(float4*)&QsT[d * 132 + ty * 8 + 4];
            *(float4*)&kr[0] = *(float4*)&KsT[d * 132 + tx * 8];
            *(float4*)&kr[4] = *(float4*)&KsT[d * 132 + tx * 8 + 4];
#pragma unroll
            for (int i = 0; i < 8; i++)
#pragma unroll
                for (int j = 0; j < 8; j++) s[i][j] += qr[i] * kr[j];
        }

#pragma unroll
        for (int i = 0; i < 8; i++) {
            int q = q0 + ty * 8 + i;
            const float* Rrow = R + (size_t)q * SS + (SS - 1 - q) + k0 + tx * 8;
#pragma unroll
            for (int j = 0; j < 8; j++) {
                float v = (s[i][j] + Rrow[j]) * 0.125f;
                int k = k0 + tx * 8 + j;
                s[i][j] = (k <= q) ? v : -1.0e30f;
            }
        }

#pragma unroll
        for (int i = 0; i < 8; i++) {
            float mt = s[i][0];
#pragma unroll
            for (int j = 1; j < 8; j++) mt = fmaxf(mt, s[i][j]);
#pragma unroll
            for (int off = 8; off > 0; off >>= 1)
                mt = fmaxf(mt, __shfl_xor_sync(0xffffffffu, mt, off));
            float mnew = fmaxf(m_i[i], mt);
            float corr = __expf(m_i[i] - mnew);
            m_i[i] = mnew;
            float rs = 0.f;
#pragma unroll
            for (int j = 0; j < 8; j++) {
                float p = __expf(s[i][j] - mnew);
                s[i][j] = p;
                rs += p;
            }
#pragma unroll
            for (int off = 8; off > 0; off >>= 1)
                rs += __shfl_xor_sync(0xffffffffu, rs, off);
            l_i[i] = l_i[i] * corr + rs;
#pragma unroll
            for (int dd = 0; dd < 4; dd++) o[i][dd] *= corr;
        }

#pragma unroll
        for (int i = 0; i < 8; i++) {
            float4 p0, p1;
            p0.x = s[i][0]; p0.y = s[i][1]; p0.z = s[i][2]; p0.w = s[i][3];
            p1.x = s[i][4]; p1.y = s[i][5]; p1.z = s[i][6]; p1.w = s[i][7];
            *(float4*)&Ps[(ty * 8 + i) * 132 + tx * 8]     = p0;
            *(float4*)&Ps[(ty * 8 + i) * 132 + tx * 8 + 4] = p1;
        }
        __syncthreads();

#pragma unroll 4
        for (int k = 0; k < 128; k++) {
            float4 vv = *(float4*)&Vs[k * 68 + tx * 4];
            float pr[8];
#pragma unroll
            for (int i = 0; i < 8; i++) pr[i] = Ps[(ty * 8 + i) * 132 + k];
#pragma unroll
            for (int i = 0; i < 8; i++) {
                o[i][0] += pr[i] * vv.x;
                o[i][1] += pr[i] * vv.y;
                o[i][2] += pr[i] * vv.z;
                o[i][3] += pr[i] * vv.w;
            }
        }
    }

    int b = bh >> 4, h = bh & 15;
#pragma unroll
    for (int i = 0; i < 8; i++) {
        float inv = 1.0f / l_i[i];
        float4 ov;
        ov.x = o[i][0] * inv;
        ov.y = o[i][1] * inv;
        ov.z = o[i][2] * inv;
        ov.w = o[i][3] * inv;
        int q = q0 + ty * 8 + i;
        *(float4*)&g_att[((size_t)(b * SS + q)) * DMM + h * 64 + tx * 4] = ov;
    }
}

// ---------------- output projection, TF32 tensor-core GEMM ----------------
__global__ __launch_bounds__(256, 2) void k_out(
    const float* __restrict__ Wo, const float* __restrict__ bo, float* __restrict__ out)
{
    __shared__ uint32_t As[2][128 * AS_STRIDE];
    __shared__ uint32_t Bs[2][16 * BS_STRIDE];

    int bn = blockIdx.x * 128, bm = blockIdx.y * 128;

    int tid = threadIdx.x;
    int lane = tid & 31, wid = tid >> 5;
    int warpM = wid >> 2, warpN = wid & 3;
    int g = lane >> 2, tg = lane & 3;
    int arow = tid >> 2, ac = (tid & 3) * 4;
    int brow = tid >> 5, bc = (tid & 31) * 4;

    const float* Ap = g_att + (size_t)(bm + arow) * DMM + ac;
    const float* Bp = Wo + (size_t)brow * DMM + bn + bc;

    {
        float4 a0 = *(const float4*)Ap;
        float4 a1 = *(const float4*)(Ap + (size_t)64 * DMM);
        float4 b0 = *(const float4*)Bp;
        float4 b1 = *(const float4*)(Bp + (size_t)8 * DMM);
        uint32_t* p;
        p = &As[0][arow * AS_STRIDE + ac];
        p[0] = f2tf(a0.x); p[1] = f2tf(a0.y); p[2] = f2tf(a0.z); p[3] = f2tf(a0.w);
        p = &As[0][(arow + 64) * AS_STRIDE + ac];
        p[0] = f2tf(a1.x); p[1] = f2tf(a1.y); p[2] = f2tf(a1.z); p[3] = f2tf(a1.w);
        p = &Bs[0][brow * BS_STRIDE + bc];
        p[0] = f2tf(b0.x); p[1] = f2tf(b0.y); p[2] = f2tf(b0.z); p[3] = f2tf(b0.w);
        p = &Bs[0][(brow + 8) * BS_STRIDE + bc];
        p[0] = f2tf(b1.x); p[1] = f2tf(b1.y); p[2] = f2tf(b1.z); p[3] = f2tf(b1.w);
    }
    __syncthreads();

    float c[4][4][4];
#pragma unroll
    for (int mt = 0; mt < 4; mt++)
#pragma unroll
        for (int nt = 0; nt < 4; nt++)
#pragma unroll
            for (int r = 0; r < 4; r++) c[mt][nt][r] = 0.f;

    for (int it = 0; it < 64; it++) {
        int cur = it & 1;
        float4 a0, a1, b0, b1;
        bool more = (it < 63);
        if (more) {
            const float* Ap2 = Ap + (it + 1) * 16;
            const float* Bp2 = Bp + (size_t)(it + 1) * 16 * DMM;
            a0 = *(const float4*)Ap2;
            a1 = *(const float4*)(Ap2 + (size_t)64 * DMM);
            b0 = *(const float4*)Bp2;
            b1 = *(const float4*)(Bp2 + (size_t)8 * DMM);
        }
#pragma unroll
        for (int ks2 = 0; ks2 < 2; ks2++) {
            int ks = ks2 * 8;
            uint32_t af[4][4], bf[4][2];
#pragma unroll
            for (int mt = 0; mt < 4; mt++) {
                int rb = warpM * 64 + mt * 16;
                af[mt][0] = As[cur][(rb + g)     * AS_STRIDE + ks + tg];
                af[mt][1] = As[cur][(rb + g + 8) * AS_STRIDE + ks + tg];
                af[mt][2] = As[cur][(rb + g)     * AS_STRIDE + ks + tg + 4];
                af[mt][3] = As[cur][(rb + g + 8) * AS_STRIDE + ks + tg + 4];
            }
#pragma unroll
            for (int nt = 0; nt < 4; nt++) {
                int cb = warpN * 32 + nt * 8;
                bf[nt][0] = Bs[cur][(ks + tg)     * BS_STRIDE + cb + g];
                bf[nt][1] = Bs[cur][(ks + tg + 4) * BS_STRIDE + cb + g];
            }
#pragma unroll
            for (int mt = 0; mt < 4; mt++)
#pragma unroll
                for (int nt = 0; nt < 4; nt++)
                    mma_tf32(c[mt][nt], af[mt], bf[nt]);
        }
        if (more) {
            int nxt = cur ^ 1;
            uint32_t* p;
            p = &As[nxt][arow * AS_STRIDE + ac];
            p[0] = f2tf(a0.x); p[1] = f2tf(a0.y); p[2] = f2tf(a0.z); p[3] = f2tf(a0.w);
            p = &As[nxt][(arow + 64) * AS_STRIDE + ac];
            p[0] = f2tf(a1.x); p[1] = f2tf(a1.y); p[2] = f2tf(a1.z); p[3] = f2tf(a1.w);
            p = &Bs[nxt][brow * BS_STRIDE + bc];
            p[0] = f2tf(b0.x); p[1] = f2tf(b0.y); p[2] = f2tf(b0.z); p[3] = f2tf(b0.w);
            p = &Bs[nxt][(brow + 8) * BS_STRIDE + bc];
            p[0] = f2tf(b1.x); p[1] = f2tf(b1.y); p[2] = f2tf(b1.z); p[3] = f2tf(b1.w);
            __syncthreads();
        }
    }

#pragma unroll
    for (int mt = 0; mt < 4; mt++) {
#pragma unroll
        for (int nt = 0; nt < 4; nt++) {
            int n = bn + warpN * 32 + nt * 8 + 2 * tg;
            float b0v = bo[n], b1v = bo[n + 1];
            int m0 = bm + warpM * 64 + mt * 16 + g;
            float2 o0; o0.x = c[mt][nt][0] + b0v; o0.y = c[mt][nt][1] + b1v;
            float2 o1; o1.x = c[mt][nt][2] + b0v; o1.y = c[mt][nt][3] + b1v;
            *(float2*)&out[(size_t)m0 * DMM + n]       = o0;
            *(float2*)&out[(size_t)(m0 + 8) * DMM + n] = o1;
        }
    }
}

// ---------------- launch ----------------
extern "C" void kernel_launch(void* const* d_in, const int* in_sizes, int n_in,
                              void* d_out, int out_size)
{
    const float* x  = (const float*)d_in[0];
    const float* Wq = (const float*)d_in[1];
    const float* bq = (const float*)d_in[2];
    const float* Wk = (const float*)d_in[3];
    const float* bk = (const float*)d_in[4];
    const float* Wv = (const float*)d_in[5];
    const float* bv = (const float*)d_in[6];
    const float* Wo = (const float*)d_in[7];
    const float* bo = (const float*)d_in[8];
    const float* Er = (const float*)d_in[9];
    float* out = (float*)d_out;

    cudaFuncSetAttribute((const void*)k_attn,
                         cudaFuncAttributeMaxDynamicSharedMemorySize,
                         ATTN_SMEM_FLOATS * (int)sizeof(float));

    k_transpose_er<<<512, 256>>>(Er);
    k_qkv<<<dim3(24, 32), 256>>>(x, Wq, Wk, Wv, bq, bk, bv);
    k_rel<<<dim3(16, 16, 32), 256>>>();
    k_attn<<<dim3(16, 32), 256, ATTN_SMEM_FLOATS * sizeof(float)>>>();
    k_out<<<dim3(8, 32), 256>>>(Wo, bo, out);
}

// round 5
// speedup vs baseline: 1.9175x; 1.1400x over previous
#include <cuda_runtime.h>
#include <cstdint>

#define BB  2
#define SS  2048
#define DMM 1024
#define HH  16
#define DHH 64
#define BH  (BB*HH)   // 32

// ---------------- scratch (device globals; no runtime allocation) ----------------
__device__ float g_q[BB*HH*SS*DHH];
__device__ float g_k[BB*HH*SS*DHH];
__device__ float g_v[BB*HH*SS*DHH];
__device__ float g_att[BB*SS*DMM];
__device__ float g_erT[DHH*SS];          // Er[0:2048] transposed: [64][2048]
__device__ float g_rel[134217728];       // PRE-SKEWED: [BH][q][k] = Q[q]·Er[k+2047-q]

// ---------------- helpers ----------------
__device__ __forceinline__ uint32_t f2tf(float f) {
    uint32_t u;
    asm("cvt.rna.tf32.f32 %0, %1;" : "=r"(u) : "f"(f));
    return u;
}

__device__ __forceinline__ void mma_tf32(float* c, const uint32_t* a, const uint32_t* b) {
    asm("mma.sync.aligned.m16n8k8.row.col.f32.tf32.tf32.f32 "
        "{%0,%1,%2,%3},{%4,%5,%6,%7},{%8,%9},{%0,%1,%2,%3};"
        : "+f"(c[0]), "+f"(c[1]), "+f"(c[2]), "+f"(c[3])
        : "r"(a[0]), "r"(a[1]), "r"(a[2]), "r"(a[3]), "r"(b[0]), "r"(b[1]));
}

// ---------------- Er transpose ----------------
__global__ void k_transpose_er(const float* __restrict__ Er) {
    int idx = blockIdx.x * 256 + threadIdx.x;   // 0 .. 64*2048-1
    int r = idx & 2047;
    int d = idx >> 11;
    g_erT[idx] = Er[r * 64 + d];
}

// ---------------- fused QKV projection, TF32 tensor-core GEMM ----------------
#define AS_STRIDE 20
#define BS_STRIDE 136
__global__ __launch_bounds__(256, 2) void k_qkv(
    const float* __restrict__ x,
    const float* __restrict__ Wq, const float* __restrict__ Wk, const float* __restrict__ Wv,
    const float* __restrict__ bq, const float* __restrict__ bk, const float* __restrict__ bv)
{
    __shared__ uint32_t As[2][128 * AS_STRIDE];
    __shared__ uint32_t Bs[2][16 * BS_STRIDE];

    int bx = blockIdx.x, by = blockIdx.y;
    int which = bx >> 3;
    const float* W    = (which == 0) ? Wq : ((which == 1) ? Wk : Wv);
    const float* bias = (which == 0) ? bq : ((which == 1) ? bk : bv);
    float*       dst  = (which == 0) ? g_q : ((which == 1) ? g_k : g_v);
    int nb = (bx & 7) * 128;
    int bm = by * 128;

    int tid = threadIdx.x;
    int lane = tid & 31, wid = tid >> 5;
    int warpM = wid >> 2, warpN = wid & 3;
    int g = lane >> 2, tg = lane & 3;
    int arow = tid >> 2, ac = (tid & 3) * 4;
    int brow = tid >> 5, bc = (tid & 31) * 4;

    const float* Ap = x + (size_t)(bm + arow) * DMM + ac;
    const float* Bp = W + (size_t)brow * DMM + nb + bc;

    {
        float4 a0 = *(const float4*)Ap;
        float4 a1 = *(const float4*)(Ap + (size_t)64 * DMM);
        float4 b0 = *(const float4*)Bp;
        float4 b1 = *(const float4*)(Bp + (size_t)8 * DMM);
        uint32_t* p;
        p = &As[0][arow * AS_STRIDE + ac];
        p[0] = f2tf(a0.x); p[1] = f2tf(a0.y); p[2] = f2tf(a0.z); p[3] = f2tf(a0.w);
        p = &As[0][(arow + 64) * AS_STRIDE + ac];
        p[0] = f2tf(a1.x); p[1] = f2tf(a1.y); p[2] = f2tf(a1.z); p[3] = f2tf(a1.w);
        p = &Bs[0][brow * BS_STRIDE + bc];
        p[0] = f2tf(b0.x); p[1] = f2tf(b0.y); p[2] = f2tf(b0.z); p[3] = f2tf(b0.w);
        p = &Bs[0][(brow + 8) * BS_STRIDE + bc];
        p[0] = f2tf(b1.x); p[1] = f2tf(b1.y); p[2] = f2tf(b1.z); p[3] = f2tf(b1.w);
    }
    __syncthreads();

    float c[4][4][4];
#pragma unroll
    for (int mt = 0; mt < 4; mt++)
#pragma unroll
        for (int nt = 0; nt < 4; nt++)
#pragma unroll
            for (int r = 0; r < 4; r++) c[mt][nt][r] = 0.f;

    for (int it = 0; it < 64; it++) {
        int cur = it & 1;
        float4 a0, a1, b0, b1;
        bool more = (it < 63);
        if (more) {
            const float* Ap2 = Ap + (it + 1) * 16;
            const float* Bp2 = Bp + (size_t)(it + 1) * 16 * DMM;
            a0 = *(const float4*)Ap2;
            a1 = *(const float4*)(Ap2 + (size_t)64 * DMM);
            b0 = *(const float4*)Bp2;
            b1 = *(const float4*)(Bp2 + (size_t)8 * DMM);
        }
#pragma unroll
        for (int ks2 = 0; ks2 < 2; ks2++) {
            int ks = ks2 * 8;
            uint32_t af[4][4], bf[4][2];
#pragma unroll
            for (int mt = 0; mt < 4; mt++) {
                int rb = warpM * 64 + mt * 16;
                af[mt][0] = As[cur][(rb + g)     * AS_STRIDE + ks + tg];
                af[mt][1] = As[cur][(rb + g + 8) * AS_STRIDE + ks + tg];
                af[mt][2] = As[cur][(rb + g)     * AS_STRIDE + ks + tg + 4];
                af[mt][3] = As[cur][(rb + g + 8) * AS_STRIDE + ks + tg + 4];
            }
#pragma unroll
            for (int nt = 0; nt < 4; nt++) {
                int cb = warpN * 32 + nt * 8;
                bf[nt][0] = Bs[cur][(ks + tg)     * BS_STRIDE + cb + g];
                bf[nt][1] = Bs[cur][(ks + tg + 4) * BS_STRIDE + cb + g];
            }
#pragma unroll
            for (int mt = 0; mt < 4; mt++)
#pragma unroll
                for (int nt = 0; nt < 4; nt++)
                    mma_tf32(c[mt][nt], af[mt], bf[nt]);
        }
        if (more) {
            int nxt = cur ^ 1;
            uint32_t* p;
            p = &As[nxt][arow * AS_STRIDE + ac];
            p[0] = f2tf(a0.x); p[1] = f2tf(a0.y); p[2] = f2tf(a0.z); p[3] = f2tf(a0.w);
            p = &As[nxt][(arow + 64) * AS_STRIDE + ac];
            p[0] = f2tf(a1.x); p[1] = f2tf(a1.y); p[2] = f2tf(a1.z); p[3] = f2tf(a1.w);
            p = &Bs[nxt][brow * BS_STRIDE + bc];
            p[0] = f2tf(b0.x); p[1] = f2tf(b0.y); p[2] = f2tf(b0.z); p[3] = f2tf(b0.w);
            p = &Bs[nxt][(brow + 8) * BS_STRIDE + bc];
            p[0] = f2tf(b1.x); p[1] = f2tf(b1.y); p[2] = f2tf(b1.z); p[3] = f2tf(b1.w);
            __syncthreads();
        }
    }

#pragma unroll
    for (int mt = 0; mt < 4; mt++) {
#pragma unroll
        for (int nt = 0; nt < 4; nt++) {
            int nloc = nb + warpN * 32 + nt * 8 + 2 * tg;
            int h = nloc >> 6, d = nloc & 63;
            float b0v = bias[nloc], b1v = bias[nloc + 1];
            int m0 = bm + warpM * 64 + mt * 16 + g;
            int m1 = m0 + 8;
            {
                int b = m0 >> 11, s = m0 & 2047;
                float2 o; o.x = c[mt][nt][0] + b0v; o.y = c[mt][nt][1] + b1v;
                *(float2*)&dst[(((size_t)b * HH + h) * SS + s) * DHH + d] = o;
            }
            {
                int b = m1 >> 11, s = m1 & 2047;
                float2 o; o.x = c[mt][nt][2] + b0v; o.y = c[mt][nt][3] + b1v;
                *(float2*)&dst[(((size_t)b * HH + h) * SS + s) * DHH + d] = o;
            }
        }
    }
}

// ---------------- REL GEMM (TF32), skewed store: g_rel[q][k] = Q[q]·Er[k+2047-q] ----------------
__global__ __launch_bounds__(256, 2) void k_rel()
{
    int bh = blockIdx.z;
    int r0 = blockIdx.x * 128, q0 = blockIdx.y * 128;
    if (q0 + r0 < 1793) return;

    __shared__ uint32_t As[2][128 * AS_STRIDE];
    __shared__ uint32_t Bs[2][16 * BS_STRIDE];

    const float* A = g_q + (size_t)bh * SS * DHH;

    int tid = threadIdx.x;
    int lane = tid & 31, wid = tid >> 5;
    int warpM = wid >> 2, warpN = wid & 3;
    int g = lane >> 2, tg = lane & 3;
    int arow = tid >> 2, ac = (tid & 3) * 4;
    int brow = tid >> 5, bc = (tid & 31) * 4;

    const float* Ap = A + (size_t)(q0 + arow) * DHH + ac;
    const float* Bp = g_erT + (size_t)brow * SS + r0 + bc;

    {
        float4 a0 = *(const float4*)Ap;
        float4 a1 = *(const float4*)(Ap + (size_t)64 * DHH);
        float4 b0 = *(const float4*)Bp;
        float4 b1 = *(const float4*)(Bp + (size_t)8 * SS);
        uint32_t* p;
        p = &As[0][arow * AS_STRIDE + ac];
        p[0] = f2tf(a0.x); p[1] = f2tf(a0.y); p[2] = f2tf(a0.z); p[3] = f2tf(a0.w);
        p = &As[0][(arow + 64) * AS_STRIDE + ac];
        p[0] = f2tf(a1.x); p[1] = f2tf(a1.y); p[2] = f2tf(a1.z); p[3] = f2tf(a1.w);
        p = &Bs[0][brow * BS_STRIDE + bc];
        p[0] = f2tf(b0.x); p[1] = f2tf(b0.y); p[2] = f2tf(b0.z); p[3] = f2tf(b0.w);
        p = &Bs[0][(brow + 8) * BS_STRIDE + bc];
        p[0] = f2tf(b1.x); p[1] = f2tf(b1.y); p[2] = f2tf(b1.z); p[3] = f2tf(b1.w);
    }
    __syncthreads();

    float c[4][4][4];
#pragma unroll
    for (int mt = 0; mt < 4; mt++)
#pragma unroll
        for (int nt = 0; nt < 4; nt++)
#pragma unroll
            for (int r = 0; r < 4; r++) c[mt][nt][r] = 0.f;

    for (int it = 0; it < 4; it++) {
        int cur = it & 1;
        float4 a0, a1, b0, b1;
        bool more = (it < 3);
        if (more) {
            const float* Ap2 = Ap + (it + 1) * 16;
            const float* Bp2 = Bp + (size_t)(it + 1) * 16 * SS;
            a0 = *(const float4*)Ap2;
            a1 = *(const float4*)(Ap2 + (size_t)64 * DHH);
            b0 = *(const float4*)Bp2;
            b1 = *(const float4*)(Bp2 + (size_t)8 * SS);
        }
#pragma unroll
        for (int ks2 = 0; ks2 < 2; ks2++) {
            int ks = ks2 * 8;
            uint32_t af[4][4], bf[4][2];
#pragma unroll
            for (int mt = 0; mt < 4; mt++) {
                int rb = warpM * 64 + mt * 16;
                af[mt][0] = As[cur][(rb + g)     * AS_STRIDE + ks + tg];
                af[mt][1] = As[cur][(rb + g + 8) * AS_STRIDE + ks + tg];
                af[mt][2] = As[cur][(rb + g)     * AS_STRIDE + ks + tg + 4];
                af[mt][3] = As[cur][(rb + g + 8) * AS_STRIDE + ks + tg + 4];
            }
#pragma unroll
            for (int nt = 0; nt < 4; nt++) {
                int cb = warpN * 32 + nt * 8;
                bf[nt][0] = Bs[cur][(ks + tg)     * BS_STRIDE + cb + g];
                bf[nt][1] = Bs[cur][(ks + tg + 4) * BS_STRIDE + cb + g];
            }
#pragma unroll
            for (int mt = 0; mt < 4; mt++)
#pragma unroll
                for (int nt = 0; nt < 4; nt++)
                    mma_tf32(c[mt][nt], af[mt], bf[nt]);
        }
        if (more) {
            int nxt = cur ^ 1;
            uint32_t* p;
            p = &As[nxt][arow * AS_STRIDE + ac];
            p[0] = f2tf(a0.x); p[1] = f2tf(a0.y); p[2] = f2tf(a0.z); p[3] = f2tf(a0.w);
            p = &As[nxt][(arow + 64) * AS_STRIDE + ac];
            p[0] = f2tf(a1.x); p[1] = f2tf(a1.y); p[2] = f2tf(a1.z); p[3] = f2tf(a1.w);
            p = &Bs[nxt][brow * BS_STRIDE + bc];
            p[0] = f2tf(b0.x); p[1] = f2tf(b0.y); p[2] = f2tf(b0.z); p[3] = f2tf(b0.w);
            p = &Bs[nxt][(brow + 8) * BS_STRIDE + bc];
            p[0] = f2tf(b1.x); p[1] = f2tf(b1.y); p[2] = f2tf(b1.z); p[3] = f2tf(b1.w);
            __syncthreads();
        }
    }

    // skewed epilogue: element (m, col) -> g_rel[m][col - (2047 - m)] when in causal band
    float* C = g_rel + (size_t)bh * SS * SS;
#pragma unroll
    for (int mt = 0; mt < 4; mt++) {
#pragma unroll
        for (int nt = 0; nt < 4; nt++) {
            int col = r0 + warpN * 32 + nt * 8 + 2 * tg;
            int m0 = q0 + warpM * 64 + mt * 16 + g;
            int m1 = m0 + 8;
            int k0e = col - 2047 + m0;
            int k1e = col - 2047 + m1;
            if (k0e >= 0)     C[(size_t)m0 * SS + k0e]     = c[mt][nt][0];
            if (k0e + 1 >= 0) C[(size_t)m0 * SS + k0e + 1] = c[mt][nt][1];
            if (k1e >= 0)     C[(size_t)m1 * SS + k1e]     = c[mt][nt][2];
            if (k1e + 1 >= 0) C[(size_t)m1 * SS + k1e + 1] = c[mt][nt][3];
        }
    }
}

// ---------------- flash attention, TF32 tensor cores ----------------
// 256 threads (8 warps x 16 q-rows = 128 q), Bk = 128.
// smem (tf32 bits): Ks[128][68] | Vs[128][72] | Ps[128][132] = 34816 u32 = 139264 B
#define ATTN_SMEM_U32 (128*68 + 128*72 + 128*132)

__global__ __launch_bounds__(256) void k_attn()
{
    extern __shared__ uint32_t smu[];
    uint32_t* Ks = smu;                 // [k][d]   stride 68
    uint32_t* Vs = Ks + 128 * 68;       // [k][d]   stride 72
    uint32_t* Ps = Vs + 128 * 72;       // [q][k]   stride 132 (per-warp-private rows)

    int bh = blockIdx.y;
    int qt = (int)gridDim.x - 1 - (int)blockIdx.x;   // heavy tiles first
    int q0 = qt * 128;
    const float* Q  = g_q + (size_t)bh * SS * DHH;
    const float* Kp = g_k + (size_t)bh * SS * DHH;
    const float* Vp = g_v + (size_t)bh * SS * DHH;
    const float* R  = g_rel + (size_t)bh * SS * SS;

    int tid = threadIdx.x;
    int lane = tid & 31, wid = tid >> 5;
    int g = lane >> 2, tg = lane & 3;
    int qbase = q0 + wid * 16;
    int qlo = qbase + g, qhi = qlo + 8;

    // Q A-fragments in registers, loaded once, reused for every k-tile
    uint32_t qa[8][4];
#pragma unroll
    for (int ks = 0; ks < 8; ks++) {
        qa[ks][0] = f2tf(Q[(size_t)qlo * DHH + ks * 8 + tg]);
        qa[ks][1] = f2tf(Q[(size_t)qhi * DHH + ks * 8 + tg]);
        qa[ks][2] = f2tf(Q[(size_t)qlo * DHH + ks * 8 + tg + 4]);
        qa[ks][3] = f2tf(Q[(size_t)qhi * DHH + ks * 8 + tg + 4]);
    }

    float o[8][4];
#pragma unroll
    for (int nt = 0; nt < 8; nt++) { o[nt][0] = o[nt][1] = o[nt][2] = o[nt][3] = 0.f; }
    float mlo = -3.0e38f, mhi = -3.0e38f, llo = 0.f, lhi = 0.f;

    for (int t = 0; t <= qt; t++) {
        int k0 = t * 128;
        __syncthreads();   // prior tile's PV reads of Vs done
#pragma unroll
        for (int i = 0; i < 8; i++) {
            int idx = i * 256 + tid;
            int ki = idx >> 4, c4 = (idx & 15) * 4;
            float4 kv = *(const float4*)&Kp[(size_t)(k0 + ki) * DHH + c4];
            uint32_t* pk = &Ks[ki * 68 + c4];
            pk[0] = f2tf(kv.x); pk[1] = f2tf(kv.y); pk[2] = f2tf(kv.z); pk[3] = f2tf(kv.w);
            float4 vv = *(const float4*)&Vp[(size_t)(k0 + ki) * DHH + c4];
            uint32_t* pv = &Vs[ki * 72 + c4];
            pv[0] = f2tf(vv.x); pv[1] = f2tf(vv.y); pv[2] = f2tf(vv.z); pv[3] = f2tf(vv.w);
        }
        __syncthreads();

        // warp-uniform causal bound: n-groups beyond qbase+15 are fully masked
        int ntmax = min(16, ((qbase + 15 - k0) >> 3) + 1);

        // ---- scores S = Q·K^T ----
        float s[16][4];
#pragma unroll
        for (int nt = 0; nt < 16; nt++) { s[nt][0] = s[nt][1] = s[nt][2] = s[nt][3] = 0.f; }
#pragma unroll
        for (int ks = 0; ks < 8; ks++) {
#pragma unroll
            for (int nt = 0; nt < 16; nt++) {
                if (nt < ntmax) {
                    uint32_t bf[2];
                    bf[0] = Ks[(nt * 8 + g) * 68 + ks * 8 + tg];
                    bf[1] = Ks[(nt * 8 + g) * 68 + ks * 8 + tg + 4];
                    mma_tf32(s[nt], qa[ks], bf);
                }
            }
        }

        // ---- + rel bias (aligned float2 rows), scale, causal mask ----
        float tmlo = -3.0e38f, tmhi = -3.0e38f;
#pragma unroll
        for (int nt = 0; nt < 16; nt++) {
            if (nt < ntmax) {
                int kk = k0 + nt * 8 + 2 * tg;
                float2 rlo = *(const float2*)&R[(size_t)qlo * SS + kk];
                float2 rhi = *(const float2*)&R[(size_t)qhi * SS + kk];
                s[nt][0] = (kk     <= qlo) ? (s[nt][0] + rlo.x) * 0.125f : -1.0e30f;
                s[nt][1] = (kk + 1 <= qlo) ? (s[nt][1] + rlo.y) * 0.125f : -1.0e30f;
                s[nt][2] = (kk     <= qhi) ? (s[nt][2] + rhi.x) * 0.125f : -1.0e30f;
                s[nt][3] = (kk + 1 <= qhi) ? (s[nt][3] + rhi.y) * 0.125f : -1.0e30f;
                tmlo = fmaxf(tmlo, fmaxf(s[nt][0], s[nt][1]));
                tmhi = fmaxf(tmhi, fmaxf(s[nt][2], s[nt][3]));
            }
        }

        // ---- online softmax (rows live in 4 tg lanes -> 2 shfls) ----
        tmlo = fmaxf(tmlo, __shfl_xor_sync(0xffffffffu, tmlo, 1));
        tmlo = fmaxf(tmlo, __shfl_xor_sync(0xffffffffu, tmlo, 2));
        tmhi = fmaxf(tmhi, __shfl_xor_sync(0xffffffffu, tmhi, 1));
        tmhi = fmaxf(tmhi, __shfl_xor_sync(0xffffffffu, tmhi, 2));
        float mnlo = fmaxf(mlo, tmlo), mnhi = fmaxf(mhi, tmhi);
        float clo = __expf(mlo - mnlo), chi = __expf(mhi - mnhi);
        mlo = mnlo; mhi = mnhi;

        float rslo = 0.f, rshi = 0.f;
        int prow_lo = (wid * 16 + g) * 132;
        int prow_hi = (wid * 16 + g + 8) * 132;
#pragma unroll
        for (int nt = 0; nt < 16; nt++) {
            if (nt < ntmax) {
                float p0 = __expf(s[nt][0] - mnlo);
                float p1 = __expf(s[nt][1] - mnlo);
                float p2 = __expf(s[nt][2] - mnhi);
                float p3 = __expf(s[nt][3] - mnhi);
                rslo += p0 + p1;
                rshi += p2 + p3;
                int col = nt * 8 + 2 * tg;
                *(uint2*)&Ps[prow_lo + col] = make_uint2(f2tf(p0), f2tf(p1));
                *(uint2*)&Ps[prow_hi + col] = make_uint2(f2tf(p2), f2tf(p3));
            }
        }
        rslo += __shfl_xor_sync(0xffffffffu, rslo, 1);
        rslo += __shfl_xor_sync(0xffffffffu, rslo, 2);
        rshi += __shfl_xor_sync(0xffffffffu, rshi, 1);
        rshi += __shfl_xor_sync(0xffffffffu, rshi, 2);
        llo = llo * clo + rslo;
        lhi = lhi * chi + rshi;
#pragma unroll
        for (int nt2 = 0; nt2 < 8; nt2++) {
            o[nt2][0] *= clo; o[nt2][1] *= clo;
            o[nt2][2] *= chi; o[nt2][3] *= chi;
        }

        __syncwarp();   // Ps rows are warp-private: warp-level ordering suffices

        // ---- O += P·V (skip k-groups where P == 0) ----
#pragma unroll
        for (int ks = 0; ks < 16; ks++) {
            if (ks < ntmax) {
                uint32_t pa[4];
                pa[0] = Ps[prow_lo + ks * 8 + tg];
                pa[1] = Ps[prow_hi + ks * 8 + tg];
                pa[2] = Ps[prow_lo + ks * 8 + tg + 4];
                pa[3] = Ps[prow_hi + ks * 8 + tg + 4];
#pragma unroll
                for (int nt2 = 0; nt2 < 8; nt2++) {
                    uint32_t bf[2];
                    bf[0] = Vs[(ks * 8 + tg)     * 72 + nt2 * 8 + g];
                    bf[1] = Vs[(ks * 8 + tg + 4) * 72 + nt2 * 8 + g];
                    mma_tf32(o[nt2], pa, bf);
                }
            }
        }
    }

    // ---- normalize + write head-interleaved [B,S,DA] ----
    float ilo = 1.0f / llo, ihi = 1.0f / lhi;
    int b = bh >> 4, h = bh & 15;
#pragma unroll
    for (int nt2 = 0; nt2 < 8; nt2++) {
        int d = nt2 * 8 + 2 * tg;
        float2 v0, v1;
        v0.x = o[nt2][0] * ilo; v0.y = o[nt2][1] * ilo;
        v1.x = o[nt2][2] * ihi; v1.y = o[nt2][3] * ihi;
        *(float2*)&g_att[((size_t)(b * SS + qlo)) * DMM + h * 64 + d] = v0;
        *(float2*)&g_att[((size_t)(b * SS + qhi)) * DMM + h * 64 + d] = v1;
    }
}

// ---------------- output projection, TF32 tensor-core GEMM ----------------
__global__ __launch_bounds__(256, 2) void k_out(
    const float* __restrict__ Wo, const float* __restrict__ bo, float* __restrict__ out)
{
    __shared__ uint32_t As[2][128 * AS_STRIDE];
    __shared__ uint32_t Bs[2][16 * BS_STRIDE];

    int bn = blockIdx.x * 128, bm = blockIdx.y * 128;

    int tid = threadIdx.x;
    int lane = tid & 31, wid = tid >> 5;
    int warpM = wid >> 2, warpN = wid & 3;
    int g = lane >> 2, tg = lane & 3;
    int arow = tid >> 2, ac = (tid & 3) * 4;
    int brow = tid >> 5, bc = (tid & 31) * 4;

    const float* Ap = g_att + (size_t)(bm + arow) * DMM + ac;
    const float* Bp = Wo + (size_t)brow * DMM + bn + bc;

    {
        float4 a0 = *(const float4*)Ap;
        float4 a1 = *(const float4*)(Ap + (size_t)64 * DMM);
        float4 b0 = *(const float4*)Bp;
        float4 b1 = *(const float4*)(Bp + (size_t)8 * DMM);
        uint32_t* p;
        p = &As[0][arow * AS_STRIDE + ac];
        p[0] = f2tf(a0.x); p[1] = f2tf(a0.y); p[2] = f2tf(a0.z); p[3] = f2tf(a0.w);
        p = &As[0][(arow + 64) * AS_STRIDE + ac];
        p[0] = f2tf(a1.x); p[1] = f2tf(a1.y); p[2] = f2tf(a1.z); p[3] = f2tf(a1.w);
        p = &Bs[0][brow * BS_STRIDE + bc];
        p[0] = f2tf(b0.x); p[1] = f2tf(b0.y); p[2] = f2tf(b0.z); p[3] = f2tf(b0.w);
        p = &Bs[0][(brow + 8) * BS_STRIDE + bc];
        p[0] = f2tf(b1.x); p[1] = f2tf(b1.y); p[2] = f2tf(b1.z); p[3] = f2tf(b1.w);
    }
    __syncthreads();

    float c[4][4][4];
#pragma unroll
    for (int mt = 0; mt < 4; mt++)
#pragma unroll
        for (int nt = 0; nt < 4; nt++)
#pragma unroll
            for (int r = 0; r < 4; r++) c[mt][nt][r] = 0.f;

    for (int it = 0; it < 64; it++) {
        int cur = it & 1;
        float4 a0, a1, b0, b1;
        bool more = (it < 63);
        if (more) {
            const float* Ap2 = Ap + (it + 1) * 16;
            const float* Bp2 = Bp + (size_t)(it + 1) * 16 * DMM;
            a0 = *(const float4*)Ap2;
            a1 = *(const float4*)(Ap2 + (size_t)64 * DMM);
            b0 = *(const float4*)Bp2;
            b1 = *(const float4*)(Bp2 + (size_t)8 * DMM);
        }
#pragma unroll
        for (int ks2 = 0; ks2 < 2; ks2++) {
            int ks = ks2 * 8;
            uint32_t af[4][4], bf[4][2];
#pragma unroll
            for (int mt = 0; mt < 4; mt++) {
                int rb = warpM * 64 + mt * 16;
                af[mt][0] = As[cur][(rb + g)     * AS_STRIDE + ks + tg];
                af[mt][1] = As[cur][(rb + g + 8) * AS_STRIDE + ks + tg];
                af[mt][2] = As[cur][(rb + g)     * AS_STRIDE + ks + tg + 4];
                af[mt][3] = As[cur][(rb + g + 8) * AS_STRIDE + ks + tg + 4];
            }
#pragma unroll
            for (int nt = 0; nt < 4; nt++) {
                int cb = warpN * 32 + nt * 8;
                bf[nt][0] = Bs[cur][(ks + tg)     * BS_STRIDE + cb + g];
                bf[nt][1] = Bs[cur][(ks + tg + 4) * BS_STRIDE + cb + g];
            }
#pragma unroll
            for (int mt = 0; mt < 4; mt++)
#pragma unroll
                for (int nt = 0; nt < 4; nt++)
                    mma_tf32(c[mt][nt], af[mt], bf[nt]);
        }
        if (more) {
            int nxt = cur ^ 1;
            uint32_t* p;
            p = &As[nxt][arow * AS_STRIDE + ac];
            p[0] = f2tf(a0.x); p[1] = f2tf(a0.y); p[2] = f2tf(a0.z); p[3] = f2tf(a0.w);
            p = &As[nxt][(arow + 64) * AS_STRIDE + ac];
            p[0] = f2tf(a1.x); p[1] = f2tf(a1.y); p[2] = f2tf(a1.z); p[3] = f2tf(a1.w);
            p = &Bs[nxt][brow * BS_STRIDE + bc];
            p[0] = f2tf(b0.x); p[1] = f2tf(b0.y); p[2] = f2tf(b0.z); p[3] = f2tf(b0.w);
            p = &Bs[nxt][(brow + 8) * BS_STRIDE + bc];
            p[0] = f2tf(b1.x); p[1] = f2tf(b1.y); p[2] = f2tf(b1.z); p[3] = f2tf(b1.w);
            __syncthreads();
        }
    }

#pragma unroll
    for (int mt = 0; mt < 4; mt++) {
#pragma unroll
        for (int nt = 0; nt < 4; nt++) {
            int n = bn + warpN * 32 + nt * 8 + 2 * tg;
            float b0v = bo[n], b1v = bo[n + 1];
            int m0 = bm + warpM * 64 + mt * 16 + g;
            float2 o0; o0.x = c[mt][nt][0] + b0v; o0.y = c[mt][nt][1] + b1v;
            float2 o1; o1.x = c[mt][nt][2] + b0v; o1.y = c[mt][nt][3] + b1v;
            *(float2*)&out[(size_t)m0 * DMM + n]       = o0;
            *(float2*)&out[(size_t)(m0 + 8) * DMM + n] = o1;
        }
    }
}

// ---------------- launch ----------------
extern "C" void kernel_launch(void* const* d_in, const int* in_sizes, int n_in,
                              void* d_out, int out_size)
{
    const float* x  = (const float*)d_in[0];
    const float* Wq = (const float*)d_in[1];
    const float* bq = (const float*)d_in[2];
    const float* Wk = (const float*)d_in[3];
    const float* bk = (const float*)d_in[4];
    const float* Wv = (const float*)d_in[5];
    const float* bv = (const float*)d_in[6];
    const float* Wo = (const float*)d_in[7];
    const float* bo = (const float*)d_in[8];
    const float* Er = (const float*)d_in[9];
    float* out = (float*)d_out;

    cudaFuncSetAttribute((const void*)k_attn,
                         cudaFuncAttributeMaxDynamicSharedMemorySize,
                         ATTN_SMEM_U32 * (int)sizeof(uint32_t));

    k_transpose_er<<<512, 256>>>(Er);
    k_qkv<<<dim3(24, 32), 256>>>(x, Wq, Wk, Wv, bq, bk, bv);
    k_rel<<<dim3(16, 16, 32), 256>>>();
    k_attn<<<dim3(16, 32), 256, ATTN_SMEM_U32 * sizeof(uint32_t)>>>();
    k_out<<<dim3(8, 32), 256>>>(Wo, bo, out);
}

// round 6
// speedup vs baseline: 2.2595x; 1.1784x over previous
#include <cuda_runtime.h>
#include <cuda_fp16.h>
#include <cstdint>

#define BB  2
#define SS  2048
#define DMM 1024
#define HH  16
#define DHH 64
#define BH  (BB*HH)   // 32

// ---------------- scratch (device globals; no runtime allocation) ----------------
__device__ float g_q[BB*HH*SS*DHH];
__device__ float g_k[BB*HH*SS*DHH];
__device__ float g_v[BB*HH*SS*DHH];
__device__ float g_att[BB*SS*DMM];
__device__ float g_erT[DHH*SS];          // Er[0:2048] transposed: [64][2048]
__device__ __half g_rel[134217728];      // PRE-SKEWED fp16: [BH][q][k] = Q[q]·Er[k+2047-q]

// ---------------- helpers ----------------
__device__ __forceinline__ uint32_t f2tf(float f) {
    uint32_t u;
    asm("cvt.rna.tf32.f32 %0, %1;" : "=r"(u) : "f"(f));
    return u;
}

__device__ __forceinline__ void mma_tf32(float* c, const uint32_t* a, const uint32_t* b) {
    asm("mma.sync.aligned.m16n8k8.row.col.f32.tf32.tf32.f32 "
        "{%0,%1,%2,%3},{%4,%5,%6,%7},{%8,%9},{%0,%1,%2,%3};"
        : "+f"(c[0]), "+f"(c[1]), "+f"(c[2]), "+f"(c[3])
        : "r"(a[0]), "r"(a[1]), "r"(a[2]), "r"(a[3]), "r"(b[0]), "r"(b[1]));
}

// ---------------- Er transpose ----------------
__global__ void k_transpose_er(const float* __restrict__ Er) {
    int idx = blockIdx.x * 256 + threadIdx.x;   // 0 .. 64*2048-1
    int r = idx & 2047;
    int d = idx >> 11;
    g_erT[idx] = Er[r * 64 + d];
}

// ---------------- fused QKV projection, TF32 tensor-core GEMM ----------------
#define AS_STRIDE 20
#define BS_STRIDE 136
__global__ __launch_bounds__(256, 2) void k_qkv(
    const float* __restrict__ x,
    const float* __restrict__ Wq, const float* __restrict__ Wk, const float* __restrict__ Wv,
    const float* __restrict__ bq, const float* __restrict__ bk, const float* __restrict__ bv)
{
    __shared__ uint32_t As[2][128 * AS_STRIDE];
    __shared__ uint32_t Bs[2][16 * BS_STRIDE];

    int bx = blockIdx.x, by = blockIdx.y;
    int which = bx >> 3;
    const float* W    = (which == 0) ? Wq : ((which == 1) ? Wk : Wv);
    const float* bias = (which == 0) ? bq : ((which == 1) ? bk : bv);
    float*       dst  = (which == 0) ? g_q : ((which == 1) ? g_k : g_v);
    int nb = (bx & 7) * 128;
    int bm = by * 128;

    int tid = threadIdx.x;
    int lane = tid & 31, wid = tid >> 5;
    int warpM = wid >> 2, warpN = wid & 3;
    int g = lane >> 2, tg = lane & 3;
    int arow = tid >> 2, ac = (tid & 3) * 4;
    int brow = tid >> 5, bc = (tid & 31) * 4;

    const float* Ap = x + (size_t)(bm + arow) * DMM + ac;
    const float* Bp = W + (size_t)brow * DMM + nb + bc;

    {
        float4 a0 = *(const float4*)Ap;
        float4 a1 = *(const float4*)(Ap + (size_t)64 * DMM);
        float4 b0 = *(const float4*)Bp;
        float4 b1 = *(const float4*)(Bp + (size_t)8 * DMM);
        uint32_t* p;
        p = &As[0][arow * AS_STRIDE + ac];
        p[0] = f2tf(a0.x); p[1] = f2tf(a0.y); p[2] = f2tf(a0.z); p[3] = f2tf(a0.w);
        p = &As[0][(arow + 64) * AS_STRIDE + ac];
        p[0] = f2tf(a1.x); p[1] = f2tf(a1.y); p[2] = f2tf(a1.z); p[3] = f2tf(a1.w);
        p = &Bs[0][brow * BS_STRIDE + bc];
        p[0] = f2tf(b0.x); p[1] = f2tf(b0.y); p[2] = f2tf(b0.z); p[3] = f2tf(b0.w);
        p = &Bs[0][(brow + 8) * BS_STRIDE + bc];
        p[0] = f2tf(b1.x); p[1] = f2tf(b1.y); p[2] = f2tf(b1.z); p[3] = f2tf(b1.w);
    }
    __syncthreads();

    float c[4][4][4];
#pragma unroll
    for (int mt = 0; mt < 4; mt++)
#pragma unroll
        for (int nt = 0; nt < 4; nt++)
#pragma unroll
            for (int r = 0; r < 4; r++) c[mt][nt][r] = 0.f;

    for (int it = 0; it < 64; it++) {
        int cur = it & 1;
        float4 a0, a1, b0, b1;
        bool more = (it < 63);
        if (more) {
            const float* Ap2 = Ap + (it + 1) * 16;
            const float* Bp2 = Bp + (size_t)(it + 1) * 16 * DMM;
            a0 = *(const float4*)Ap2;
            a1 = *(const float4*)(Ap2 + (size_t)64 * DMM);
            b0 = *(const float4*)Bp2;
            b1 = *(const float4*)(Bp2 + (size_t)8 * DMM);
        }
#pragma unroll
        for (int ks2 = 0; ks2 < 2; ks2++) {
            int ks = ks2 * 8;
            uint32_t af[4][4], bf[4][2];
#pragma unroll
            for (int mt = 0; mt < 4; mt++) {
                int rb = warpM * 64 + mt * 16;
                af[mt][0] = As[cur][(rb + g)     * AS_STRIDE + ks + tg];
                af[mt][1] = As[cur][(rb + g + 8) * AS_STRIDE + ks + tg];
                af[mt][2] = As[cur][(rb + g)     * AS_STRIDE + ks + tg + 4];
                af[mt][3] = As[cur][(rb + g + 8) * AS_STRIDE + ks + tg + 4];
            }
#pragma unroll
            for (int nt = 0; nt < 4; nt++) {
                int cb = warpN * 32 + nt * 8;
                bf[nt][0] = Bs[cur][(ks + tg)     * BS_STRIDE + cb + g];
                bf[nt][1] = Bs[cur][(ks + tg + 4) * BS_STRIDE + cb + g];
            }
#pragma unroll
            for (int mt = 0; mt < 4; mt++)
#pragma unroll
                for (int nt = 0; nt < 4; nt++)
                    mma_tf32(c[mt][nt], af[mt], bf[nt]);
        }
        if (more) {
            int nxt = cur ^ 1;
            uint32_t* p;
            p = &As[nxt][arow * AS_STRIDE + ac];
            p[0] = f2tf(a0.x); p[1] = f2tf(a0.y); p[2] = f2tf(a0.z); p[3] = f2tf(a0.w);
            p = &As[nxt][(arow + 64) * AS_STRIDE + ac];
            p[0] = f2tf(a1.x); p[1] = f2tf(a1.y); p[2] = f2tf(a1.z); p[3] = f2tf(a1.w);
            p = &Bs[nxt][brow * BS_STRIDE + bc];
            p[0] = f2tf(b0.x); p[1] = f2tf(b0.y); p[2] = f2tf(b0.z); p[3] = f2tf(b0.w);
            p = &Bs[nxt][(brow + 8) * BS_STRIDE + bc];
            p[0] = f2tf(b1.x); p[1] = f2tf(b1.y); p[2] = f2tf(b1.z); p[3] = f2tf(b1.w);
            __syncthreads();
        }
    }

#pragma unroll
    for (int mt = 0; mt < 4; mt++) {
#pragma unroll
        for (int nt = 0; nt < 4; nt++) {
            int nloc = nb + warpN * 32 + nt * 8 + 2 * tg;
            int h = nloc >> 6, d = nloc & 63;
            float b0v = bias[nloc], b1v = bias[nloc + 1];
            int m0 = bm + warpM * 64 + mt * 16 + g;
            int m1 = m0 + 8;
            {
                int b = m0 >> 11, s = m0 & 2047;
                float2 o; o.x = c[mt][nt][0] + b0v; o.y = c[mt][nt][1] + b1v;
                *(float2*)&dst[(((size_t)b * HH + h) * SS + s) * DHH + d] = o;
            }
            {
                int b = m1 >> 11, s = m1 & 2047;
                float2 o; o.x = c[mt][nt][2] + b0v; o.y = c[mt][nt][3] + b1v;
                *(float2*)&dst[(((size_t)b * HH + h) * SS + s) * DHH + d] = o;
            }
        }
    }
}

// ---------------- REL GEMM (TF32), skewed fp16 store: g_rel[q][k] = Q[q]·Er[k+2047-q] ----------------
__global__ __launch_bounds__(256, 2) void k_rel()
{
    int bh = blockIdx.z;
    int r0 = blockIdx.x * 128, q0 = blockIdx.y * 128;
    if (q0 + r0 < 1793) return;

    __shared__ uint32_t As[2][128 * AS_STRIDE];
    __shared__ uint32_t Bs[2][16 * BS_STRIDE];

    const float* A = g_q + (size_t)bh * SS * DHH;

    int tid = threadIdx.x;
    int lane = tid & 31, wid = tid >> 5;
    int warpM = wid >> 2, warpN = wid & 3;
    int g = lane >> 2, tg = lane & 3;
    int arow = tid >> 2, ac = (tid & 3) * 4;
    int brow = tid >> 5, bc = (tid & 31) * 4;

    const float* Ap = A + (size_t)(q0 + arow) * DHH + ac;
    const float* Bp = g_erT + (size_t)brow * SS + r0 + bc;

    {
        float4 a0 = *(const float4*)Ap;
        float4 a1 = *(const float4*)(Ap + (size_t)64 * DHH);
        float4 b0 = *(const float4*)Bp;
        float4 b1 = *(const float4*)(Bp + (size_t)8 * SS);
        uint32_t* p;
        p = &As[0][arow * AS_STRIDE + ac];
        p[0] = f2tf(a0.x); p[1] = f2tf(a0.y); p[2] = f2tf(a0.z); p[3] = f2tf(a0.w);
        p = &As[0][(arow + 64) * AS_STRIDE + ac];
        p[0] = f2tf(a1.x); p[1] = f2tf(a1.y); p[2] = f2tf(a1.z); p[3] = f2tf(a1.w);
        p = &Bs[0][brow * BS_STRIDE + bc];
        p[0] = f2tf(b0.x); p[1] = f2tf(b0.y); p[2] = f2tf(b0.z); p[3] = f2tf(b0.w);
        p = &Bs[0][(brow + 8) * BS_STRIDE + bc];
        p[0] = f2tf(b1.x); p[1] = f2tf(b1.y); p[2] = f2tf(b1.z); p[3] = f2tf(b1.w);
    }
    __syncthreads();

    float c[4][4][4];
#pragma unroll
    for (int mt = 0; mt < 4; mt++)
#pragma unroll
        for (int nt = 0; nt < 4; nt++)
#pragma unroll
            for (int r = 0; r < 4; r++) c[mt][nt][r] = 0.f;

    for (int it = 0; it < 4; it++) {
        int cur = it & 1;
        float4 a0, a1, b0, b1;
        bool more = (it < 3);
        if (more) {
            const float* Ap2 = Ap + (it + 1) * 16;
            const float* Bp2 = Bp + (size_t)(it + 1) * 16 * SS;
            a0 = *(const float4*)Ap2;
            a1 = *(const float4*)(Ap2 + (size_t)64 * DHH);
            b0 = *(const float4*)Bp2;
            b1 = *(const float4*)(Bp2 + (size_t)8 * SS);
        }
#pragma unroll
        for (int ks2 = 0; ks2 < 2; ks2++) {
            int ks = ks2 * 8;
            uint32_t af[4][4], bf[4][2];
#pragma unroll
            for (int mt = 0; mt < 4; mt++) {
                int rb = warpM * 64 + mt * 16;
                af[mt][0] = As[cur][(rb + g)     * AS_STRIDE + ks + tg];
                af[mt][1] = As[cur][(rb + g + 8) * AS_STRIDE + ks + tg];
                af[mt][2] = As[cur][(rb + g)     * AS_STRIDE + ks + tg + 4];
                af[mt][3] = As[cur][(rb + g + 8) * AS_STRIDE + ks + tg + 4];
            }
#pragma unroll
            for (int nt = 0; nt < 4; nt++) {
                int cb = warpN * 32 + nt * 8;
                bf[nt][0] = Bs[cur][(ks + tg)     * BS_STRIDE + cb + g];
                bf[nt][1] = Bs[cur][(ks + tg + 4) * BS_STRIDE + cb + g];
            }
#pragma unroll
            for (int mt = 0; mt < 4; mt++)
#pragma unroll
                for (int nt = 0; nt < 4; nt++)
                    mma_tf32(c[mt][nt], af[mt], bf[nt]);
        }
        if (more) {
            int nxt = cur ^ 1;
            uint32_t* p;
            p = &As[nxt][arow * AS_STRIDE + ac];
            p[0] = f2tf(a0.x); p[1] = f2tf(a0.y); p[2] = f2tf(a0.z); p[3] = f2tf(a0.w);
            p = &As[nxt][(arow + 64) * AS_STRIDE + ac];
            p[0] = f2tf(a1.x); p[1] = f2tf(a1.y); p[2] = f2tf(a1.z); p[3] = f2tf(a1.w);
            p = &Bs[nxt][brow * BS_STRIDE + bc];
            p[0] = f2tf(b0.x); p[1] = f2tf(b0.y); p[2] = f2tf(b0.z); p[3] = f2tf(b0.w);
            p = &Bs[nxt][(brow + 8) * BS_STRIDE + bc];
            p[0] = f2tf(b1.x); p[1] = f2tf(b1.y); p[2] = f2tf(b1.z); p[3] = f2tf(b1.w);
            __syncthreads();
        }
    }

    // skewed epilogue: element (m, col) -> g_rel[m][col - (2047 - m)] when in causal band
    __half* C = g_rel + (size_t)bh * SS * SS;
#pragma unroll
    for (int mt = 0; mt < 4; mt++) {
#pragma unroll
        for (int nt = 0; nt < 4; nt++) {
            int col = r0 + warpN * 32 + nt * 8 + 2 * tg;
            int m0 = q0 + warpM * 64 + mt * 16 + g;
            int m1 = m0 + 8;
            int k0e = col - 2047 + m0;
            int k1e = col - 2047 + m1;
            if (k0e >= 0)     C[(size_t)m0 * SS + k0e]     = __float2half(c[mt][nt][0]);
            if (k0e + 1 >= 0) C[(size_t)m0 * SS + k0e + 1] = __float2half(c[mt][nt][1]);
            if (k1e >= 0)     C[(size_t)m1 * SS + k1e]     = __float2half(c[mt][nt][2]);
            if (k1e + 1 >= 0) C[(size_t)m1 * SS + k1e + 1] = __float2half(c[mt][nt][3]);
        }
    }
}

// ---------------- flash attention, TF32 tensor cores, 512 threads ----------------
// 16 warps x 16 q-rows = 256 q per block; Bk = 64.
// smem (u32): Ks[64][68] | Vs[64][72] | Ps[256][68] = 26368 u32 = 105472 B
#define ATTN_SMEM_U32 (64*68 + 64*72 + 256*68)

__global__ __launch_bounds__(512) void k_attn()
{
    extern __shared__ uint32_t smu[];
    uint32_t* Ks = smu;                 // [k][d]   stride 68
    uint32_t* Vs = Ks + 64 * 68;        // [k][d]   stride 72
    uint32_t* Ps = Vs + 64 * 72;        // [q][k]   stride 68 (per-warp-private rows)

    int bh = blockIdx.y;
    int qt = (int)gridDim.x - 1 - (int)blockIdx.x;   // heavy tiles first
    int q0 = qt * 256;
    const float*  Q  = g_q + (size_t)bh * SS * DHH;
    const float*  Kp = g_k + (size_t)bh * SS * DHH;
    const float*  Vp = g_v + (size_t)bh * SS * DHH;
    const __half* R  = g_rel + (size_t)bh * SS * SS;

    int tid = threadIdx.x;
    int lane = tid & 31, wid = tid >> 5;   // wid 0..15
    int g = lane >> 2, tg = lane & 3;
    int qbase = q0 + wid * 16;
    int qlo = qbase + g, qhi = qlo + 8;

    // Q A-fragments in registers, loaded once, reused for every k-tile
    uint32_t qa[8][4];
#pragma unroll
    for (int ks = 0; ks < 8; ks++) {
        qa[ks][0] = f2tf(Q[(size_t)qlo * DHH + ks * 8 + tg]);
        qa[ks][1] = f2tf(Q[(size_t)qhi * DHH + ks * 8 + tg]);
        qa[ks][2] = f2tf(Q[(size_t)qlo * DHH + ks * 8 + tg + 4]);
        qa[ks][3] = f2tf(Q[(size_t)qhi * DHH + ks * 8 + tg + 4]);
    }

    float o[8][4];
#pragma unroll
    for (int nt = 0; nt < 8; nt++) { o[nt][0] = o[nt][1] = o[nt][2] = o[nt][3] = 0.f; }
    float mlo = -3.0e38f, mhi = -3.0e38f, llo = 0.f, lhi = 0.f;

    int prow_lo = (wid * 16 + g) * 68;
    int prow_hi = (wid * 16 + g + 8) * 68;

    int ntiles = 4 * qt + 4;   // k up to q0+255
    for (int t = 0; t < ntiles; t++) {
        int k0 = t * 64;
        __syncthreads();   // prior tile's PV reads of Vs done
#pragma unroll
        for (int i = 0; i < 2; i++) {
            int idx = i * 512 + tid;               // 0..1023
            int ki = idx >> 4, c4 = (idx & 15) * 4;
            float4 kv = *(const float4*)&Kp[(size_t)(k0 + ki) * DHH + c4];
            uint32_t* pk = &Ks[ki * 68 + c4];
            pk[0] = f2tf(kv.x); pk[1] = f2tf(kv.y); pk[2] = f2tf(kv.z); pk[3] = f2tf(kv.w);
            float4 vv = *(const float4*)&Vp[(size_t)(k0 + ki) * DHH + c4];
            uint32_t* pv = &Vs[ki * 72 + c4];
            pv[0] = f2tf(vv.x); pv[1] = f2tf(vv.y); pv[2] = f2tf(vv.z); pv[3] = f2tf(vv.w);
        }
        __syncthreads();

        // warp-uniform causal bound (can be <= 0 for low warps at late tiles)
        int ntmax = min(8, ((qbase + 15 - k0) >> 3) + 1);
        if (ntmax > 0) {
            // ---- scores S = Q·K^T ----
            float s[8][4];
#pragma unroll
            for (int nt = 0; nt < 8; nt++) { s[nt][0] = s[nt][1] = s[nt][2] = s[nt][3] = 0.f; }
#pragma unroll
            for (int ks = 0; ks < 8; ks++) {
#pragma unroll
                for (int nt = 0; nt < 8; nt++) {
                    if (nt < ntmax) {
                        uint32_t bf[2];
                        bf[0] = Ks[(nt * 8 + g) * 68 + ks * 8 + tg];
                        bf[1] = Ks[(nt * 8 + g) * 68 + ks * 8 + tg + 4];
                        mma_tf32(s[nt], qa[ks], bf);
                    }
                }
            }

            // ---- + rel bias (fp16, aligned half2), scale, causal mask ----
            float tmlo = -3.0e38f, tmhi = -3.0e38f;
#pragma unroll
            for (int nt = 0; nt < 8; nt++) {
                if (nt < ntmax) {
                    int kk = k0 + nt * 8 + 2 * tg;
                    float2 rlo = __half22float2(*(const __half2*)&R[(size_t)qlo * SS + kk]);
                    float2 rhi = __half22float2(*(const __half2*)&R[(size_t)qhi * SS + kk]);
                    s[nt][0] = (kk     <= qlo) ? (s[nt][0] + rlo.x) * 0.125f : -1.0e30f;
                    s[nt][1] = (kk + 1 <= qlo) ? (s[nt][1] + rlo.y) * 0.125f : -1.0e30f;
                    s[nt][2] = (kk     <= qhi) ? (s[nt][2] + rhi.x) * 0.125f : -1.0e30f;
                    s[nt][3] = (kk + 1 <= qhi) ? (s[nt][3] + rhi.y) * 0.125f : -1.0e30f;
                    tmlo = fmaxf(tmlo, fmaxf(s[nt][0], s[nt][1]));
                    tmhi = fmaxf(tmhi, fmaxf(s[nt][2], s[nt][3]));
                }
            }

            // ---- online softmax (rows live in 4 tg lanes -> 2 shfls) ----
            tmlo = fmaxf(tmlo, __shfl_xor_sync(0xffffffffu, tmlo, 1));
            tmlo = fmaxf(tmlo, __shfl_xor_sync(0xffffffffu, tmlo, 2));
            tmhi = fmaxf(tmhi, __shfl_xor_sync(0xffffffffu, tmhi, 1));
            tmhi = fmaxf(tmhi, __shfl_xor_sync(0xffffffffu, tmhi, 2));
            float mnlo = fmaxf(mlo, tmlo), mnhi = fmaxf(mhi, tmhi);
            float clo = __expf(mlo - mnlo), chi = __expf(mhi - mnhi);
            mlo = mnlo; mhi = mnhi;

            float rslo = 0.f, rshi = 0.f;
#pragma unroll
            for (int nt = 0; nt < 8; nt++) {
                if (nt < ntmax) {
                    float p0 = __expf(s[nt][0] - mnlo);
                    float p1 = __expf(s[nt][1] - mnlo);
                    float p2 = __expf(s[nt][2] - mnhi);
                    float p3 = __expf(s[nt][3] - mnhi);
                    rslo += p0 + p1;
                    rshi += p2 + p3;
                    int col = nt * 8 + 2 * tg;
                    *(uint2*)&Ps[prow_lo + col] = make_uint2(f2tf(p0), f2tf(p1));
                    *(uint2*)&Ps[prow_hi + col] = make_uint2(f2tf(p2), f2tf(p3));
                }
            }
            rslo += __shfl_xor_sync(0xffffffffu, rslo, 1);
            rslo += __shfl_xor_sync(0xffffffffu, rslo, 2);
            rshi += __shfl_xor_sync(0xffffffffu, rshi, 1);
            rshi += __shfl_xor_sync(0xffffffffu, rshi, 2);
            llo = llo * clo + rslo;
            lhi = lhi * chi + rshi;
#pragma unroll
            for (int nt2 = 0; nt2 < 8; nt2++) {
                o[nt2][0] *= clo; o[nt2][1] *= clo;
                o[nt2][2] *= chi; o[nt2][3] *= chi;
            }

            __syncwarp();   // Ps rows are warp-private: warp-level ordering suffices

            // ---- O += P·V (skip k-groups where P == 0) ----
#pragma unroll
            for (int ks = 0; ks < 8; ks++) {
                if (ks < ntmax) {
                    uint32_t pa[4];
                    pa[0] = Ps[prow_lo + ks * 8 + tg];
                    pa[1] = Ps[prow_hi + ks * 8 + tg];
                    pa[2] = Ps[prow_lo + ks * 8 + tg + 4];
                    pa[3] = Ps[prow_hi + ks * 8 + tg + 4];
#pragma unroll
                    for (int nt2 = 0; nt2 < 8; nt2++) {
                        uint32_t bf[2];
                        bf[0] = Vs[(ks * 8 + tg)     * 72 + nt2 * 8 + g];
                        bf[1] = Vs[(ks * 8 + tg + 4) * 72 + nt2 * 8 + g];
                        mma_tf32(o[nt2], pa, bf);
                    }
                }
            }
        }
    }

    // ---- normalize + write head-interleaved [B,S,DA] ----
    float ilo = 1.0f / llo, ihi = 1.0f / lhi;
    int b = bh >> 4, h = bh & 15;
#pragma unroll
    for (int nt2 = 0; nt2 < 8; nt2++) {
        int d = nt2 * 8 + 2 * tg;
        float2 v0, v1;
        v0.x = o[nt2][0] * ilo; v0.y = o[nt2][1] * ilo;
        v1.x = o[nt2][2] * ihi; v1.y = o[nt2][3] * ihi;
        *(float2*)&g_att[((size_t)(b * SS + qlo)) * DMM + h * 64 + d] = v0;
        *(float2*)&g_att[((size_t)(b * SS + qhi)) * DMM + h * 64 + d] = v1;
    }
}

// ---------------- output projection, TF32 tensor-core GEMM ----------------
__global__ __launch_bounds__(256, 2) void k_out(
    const float* __restrict__ Wo, const float* __restrict__ bo, float* __restrict__ out)
{
    __shared__ uint32_t As[2][128 * AS_STRIDE];
    __shared__ uint32_t Bs[2][16 * BS_STRIDE];

    int bn = blockIdx.x * 128, bm = blockIdx.y * 128;

    int tid = threadIdx.x;
    int lane = tid & 31, wid = tid >> 5;
    int warpM = wid >> 2, warpN = wid & 3;
    int g = lane >> 2, tg = lane & 3;
    int arow = tid >> 2, ac = (tid & 3) * 4;
    int brow = tid >> 5, bc = (tid & 31) * 4;

    const float* Ap = g_att + (size_t)(bm + arow) * DMM + ac;
    const float* Bp = Wo + (size_t)brow * DMM + bn + bc;

    {
        float4 a0 = *(const float4*)Ap;
        float4 a1 = *(const float4*)(Ap + (size_t)64 * DMM);
        float4 b0 = *(const float4*)Bp;
        float4 b1 = *(const float4*)(Bp + (size_t)8 * DMM);
        uint32_t* p;
        p = &As[0][arow * AS_STRIDE + ac];
        p[0] = f2tf(a0.x); p[1] = f2tf(a0.y); p[2] = f2tf(a0.z); p[3] = f2tf(a0.w);
        p = &As[0][(arow + 64) * AS_STRIDE + ac];
        p[0] = f2tf(a1.x); p[1] = f2tf(a1.y); p[2] = f2tf(a1.z); p[3] = f2tf(a1.w);
        p = &Bs[0][brow * BS_STRIDE + bc];
        p[0] = f2tf(b0.x); p[1] = f2tf(b0.y); p[2] = f2tf(b0.z); p[3] = f2tf(b0.w);
        p = &Bs[0][(brow + 8) * BS_STRIDE + bc];
        p[0] = f2tf(b1.x); p[1] = f2tf(b1.y); p[2] = f2tf(b1.z); p[3] = f2tf(b1.w);
    }
    __syncthreads();

    float c[4][4][4];
#pragma unroll
    for (int mt = 0; mt < 4; mt++)
#pragma unroll
        for (int nt = 0; nt < 4; nt++)
#pragma unroll
            for (int r = 0; r < 4; r++) c[mt][nt][r] = 0.f;

    for (int it = 0; it < 64; it++) {
        int cur = it & 1;
        float4 a0, a1, b0, b1;
        bool more = (it < 63);
        if (more) {
            const float* Ap2 = Ap + (it + 1) * 16;
            const float* Bp2 = Bp + (size_t)(it + 1) * 16 * DMM;
            a0 = *(const float4*)Ap2;
            a1 = *(const float4*)(Ap2 + (size_t)64 * DMM);
            b0 = *(const float4*)Bp2;
            b1 = *(const float4*)(Bp2 + (size_t)8 * DMM);
        }
#pragma unroll
        for (int ks2 = 0; ks2 < 2; ks2++) {
            int ks = ks2 * 8;
            uint32_t af[4][4], bf[4][2];
#pragma unroll
            for (int mt = 0; mt < 4; mt++) {
                int rb = warpM * 64 + mt * 16;
                af[mt][0] = As[cur][(rb + g)     * AS_STRIDE + ks + tg];
                af[mt][1] = As[cur][(rb + g + 8) * AS_STRIDE + ks + tg];
                af[mt][2] = As[cur][(rb + g)     * AS_STRIDE + ks + tg + 4];
                af[mt][3] = As[cur][(rb + g + 8) * AS_STRIDE + ks + tg + 4];
            }
#pragma unroll
            for (int nt = 0; nt < 4; nt++) {
                int cb = warpN * 32 + nt * 8;
                bf[nt][0] = Bs[cur][(ks + tg)     * BS_STRIDE + cb + g];
                bf[nt][1] = Bs[cur][(ks + tg + 4) * BS_STRIDE + cb + g];
            }
#pragma unroll
            for (int mt = 0; mt < 4; mt++)
#pragma unroll
                for (int nt = 0; nt < 4; nt++)
                    mma_tf32(c[mt][nt], af[mt], bf[nt]);
        }
        if (more) {
            int nxt = cur ^ 1;
            uint32_t* p;
            p = &As[nxt][arow * AS_STRIDE + ac];
            p[0] = f2tf(a0.x); p[1] = f2tf(a0.y); p[2] = f2tf(a0.z); p[3] = f2tf(a0.w);
            p = &As[nxt][(arow + 64) * AS_STRIDE + ac];
            p[0] = f2tf(a1.x); p[1] = f2tf(a1.y); p[2] = f2tf(a1.z); p[3] = f2tf(a1.w);
            p = &Bs[nxt][brow * BS_STRIDE + bc];
            p[0] = f2tf(b0.x); p[1] = f2tf(b0.y); p[2] = f2tf(b0.z); p[3] = f2tf(b0.w);
            p = &Bs[nxt][(brow + 8) * BS_STRIDE + bc];
            p[0] = f2tf(b1.x); p[1] = f2tf(b1.y); p[2] = f2tf(b1.z); p[3] = f2tf(b1.w);
            __syncthreads();
        }
    }

#pragma unroll
    for (int mt = 0; mt < 4; mt++) {
#pragma unroll
        for (int nt = 0; nt < 4; nt++) {
            int n = bn + warpN * 32 + nt * 8 + 2 * tg;
            float b0v = bo[n], b1v = bo[n + 1];
            int m0 = bm + warpM * 64 + mt * 16 + g;
            float2 o0; o0.x = c[mt][nt][0] + b0v; o0.y = c[mt][nt][1] + b1v;
            float2 o1; o1.x = c[mt][nt][2] + b0v; o1.y = c[mt][nt][3] + b1v;
            *(float2*)&out[(size_t)m0 * DMM + n]       = o0;
            *(float2*)&out[(size_t)(m0 + 8) * DMM + n] = o1;
        }
    }
}

// ---------------- launch ----------------
extern "C" void kernel_launch(void* const* d_in, const int* in_sizes, int n_in,
                              void* d_out, int out_size)
{
    const float* x  = (const float*)d_in[0];
    const float* Wq = (const float*)d_in[1];
    const float* bq = (const float*)d_in[2];
    const float* Wk = (const float*)d_in[3];
    const float* bk = (const float*)d_in[4];
    const float* Wv = (const float*)d_in[5];
    const float* bv = (const float*)d_in[6];
    const float* Wo = (const float*)d_in[7];
    const float* bo = (const float*)d_in[8];
    const float* Er = (const float*)d_in[9];
    float* out = (float*)d_out;

    cudaFuncSetAttribute((const void*)k_attn,
                         cudaFuncAttributeMaxDynamicSharedMemorySize,
                         ATTN_SMEM_U32 * (int)sizeof(uint32_t));

    k_transpose_er<<<512, 256>>>(Er);
    k_qkv<<<dim3(24, 32), 256>>>(x, Wq, Wk, Wv, bq, bk, bv);
    k_rel<<<dim3(16, 16, 32), 256>>>();
    k_attn<<<dim3(8, 32), 512, ATTN_SMEM_U32 * sizeof(uint32_t)>>>();
    k_out<<<dim3(8, 32), 256>>>(Wo, bo, out);
}

// round 10
// speedup vs baseline: 2.3447x; 1.0377x over previous
#include <cuda_runtime.h>
#include <cuda_fp16.h>
#include <cstdint>

#define BB  2
#define SS  2048
#define DMM 1024
#define HH  16
#define DHH 64
#define BH  (BB*HH)   // 32

// ---------------- scratch (device globals; no runtime allocation) ----------------
__device__ float g_q[BB*HH*SS*DHH];
__device__ float g_k[BB*HH*SS*DHH];
__device__ float g_v[BB*HH*SS*DHH];
__device__ float g_att[BB*SS*DMM];
__device__ float g_erT[DHH*SS];          // Er[0:2048] transposed: [64][2048]
__device__ __half g_rel[134217728];      // PRE-SKEWED fp16: [BH][q][k] = Q[q]·Er[k+2047-q]

// ---------------- helpers ----------------
__device__ __forceinline__ uint32_t f2tf(float f) {
    uint32_t u;
    asm("cvt.rna.tf32.f32 %0, %1;" : "=r"(u) : "f"(f));
    return u;
}

__device__ __forceinline__ void mma_tf32(float* c, const uint32_t* a, const uint32_t* b) {
    asm("mma.sync.aligned.m16n8k8.row.col.f32.tf32.tf32.f32 "
        "{%0,%1,%2,%3},{%4,%5,%6,%7},{%8,%9},{%0,%1,%2,%3};"
        : "+f"(c[0]), "+f"(c[1]), "+f"(c[2]), "+f"(c[3])
        : "r"(a[0]), "r"(a[1]), "r"(a[2]), "r"(a[3]), "r"(b[0]), "r"(b[1]));
}

// ---------------- Er transpose ----------------
__global__ void k_transpose_er(const float* __restrict__ Er) {
    int idx = blockIdx.x * 256 + threadIdx.x;   // 0 .. 64*2048-1
    int r = idx & 2047;
    int d = idx >> 11;
    g_erT[idx] = Er[r * 64 + d];
}

// ---------------- fused QKV projection, TF32 tensor-core GEMM ----------------
#define AS_STRIDE 20
#define BS_STRIDE 136
__global__ __launch_bounds__(256, 2) void k_qkv(
    const float* __restrict__ x,
    const float* __restrict__ Wq, const float* __restrict__ Wk, const float* __restrict__ Wv,
    const float* __restrict__ bq, const float* __restrict__ bk, const float* __restrict__ bv)
{
    __shared__ uint32_t As[2][128 * AS_STRIDE];
    __shared__ uint32_t Bs[2][16 * BS_STRIDE];

    int bx = blockIdx.x, by = blockIdx.y;
    int which = bx >> 3;
    const float* W    = (which == 0) ? Wq : ((which == 1) ? Wk : Wv);
    const float* bias = (which == 0) ? bq : ((which == 1) ? bk : bv);
    float*       dst  = (which == 0) ? g_q : ((which == 1) ? g_k : g_v);
    int nb = (bx & 7) * 128;
    int bm = by * 128;

    int tid = threadIdx.x;
    int lane = tid & 31, wid = tid >> 5;
    int warpM = wid >> 2, warpN = wid & 3;
    int g = lane >> 2, tg = lane & 3;
    int arow = tid >> 2, ac = (tid & 3) * 4;
    int brow = tid >> 5, bc = (tid & 31) * 4;

    const float* Ap = x + (size_t)(bm + arow) * DMM + ac;
    const float* Bp = W + (size_t)brow * DMM + nb + bc;

    {
        float4 a0 = *(const float4*)Ap;
        float4 a1 = *(const float4*)(Ap + (size_t)64 * DMM);
        float4 b0 = *(const float4*)Bp;
        float4 b1 = *(const float4*)(Bp + (size_t)8 * DMM);
        uint32_t* p;
        p = &As[0][arow * AS_STRIDE + ac];
        p[0] = f2tf(a0.x); p[1] = f2tf(a0.y); p[2] = f2tf(a0.z); p[3] = f2tf(a0.w);
        p = &As[0][(arow + 64) * AS_STRIDE + ac];
        p[0] = f2tf(a1.x); p[1] = f2tf(a1.y); p[2] = f2tf(a1.z); p[3] = f2tf(a1.w);
        p = &Bs[0][brow * BS_STRIDE + bc];
        p[0] = f2tf(b0.x); p[1] = f2tf(b0.y); p[2] = f2tf(b0.z); p[3] = f2tf(b0.w);
        p = &Bs[0][(brow + 8) * BS_STRIDE + bc];
        p[0] = f2tf(b1.x); p[1] = f2tf(b1.y); p[2] = f2tf(b1.z); p[3] = f2tf(b1.w);
    }
    __syncthreads();

    float c[4][4][4];
#pragma unroll
    for (int mt = 0; mt < 4; mt++)
#pragma unroll
        for (int nt = 0; nt < 4; nt++)
#pragma unroll
            for (int r = 0; r < 4; r++) c[mt][nt][r] = 0.f;

    for (int it = 0; it < 64; it++) {
        int cur = it & 1;
        float4 a0, a1, b0, b1;
        bool more = (it < 63);
        if (more) {
            const float* Ap2 = Ap + (it + 1) * 16;
            const float* Bp2 = Bp + (size_t)(it + 1) * 16 * DMM;
            a0 = *(const float4*)Ap2;
            a1 = *(const float4*)(Ap2 + (size_t)64 * DMM);
            b0 = *(const float4*)Bp2;
            b1 = *(const float4*)(Bp2 + (size_t)8 * DMM);
        }
#pragma unroll
        for (int ks2 = 0; ks2 < 2; ks2++) {
            int ks = ks2 * 8;
            uint32_t af[4][4], bf[4][2];
#pragma unroll
            for (int mt = 0; mt < 4; mt++) {
                int rb = warpM * 64 + mt * 16;
                af[mt][0] = As[cur][(rb + g)     * AS_STRIDE + ks + tg];
                af[mt][1] = As[cur][(rb + g + 8) * AS_STRIDE + ks + tg];
                af[mt][2] = As[cur][(rb + g)     * AS_STRIDE + ks + tg + 4];
                af[mt][3] = As[cur][(rb + g + 8) * AS_STRIDE + ks + tg + 4];
            }
#pragma unroll
            for (int nt = 0; nt < 4; nt++) {
                int cb = warpN * 32 + nt * 8;
                bf[nt][0] = Bs[cur][(ks + tg)     * BS_STRIDE + cb + g];
                bf[nt][1] = Bs[cur][(ks + tg + 4) * BS_STRIDE + cb + g];
            }
#pragma unroll
            for (int mt = 0; mt < 4; mt++)
#pragma unroll
                for (int nt = 0; nt < 4; nt++)
                    mma_tf32(c[mt][nt], af[mt], bf[nt]);
        }
        if (more) {
            int nxt = cur ^ 1;
            uint32_t* p;
            p = &As[nxt][arow * AS_STRIDE + ac];
            p[0] = f2tf(a0.x); p[1] = f2tf(a0.y); p[2] = f2tf(a0.z); p[3] = f2tf(a0.w);
            p = &As[nxt][(arow + 64) * AS_STRIDE + ac];
            p[0] = f2tf(a1.x); p[1] = f2tf(a1.y); p[2] = f2tf(a1.z); p[3] = f2tf(a1.w);
            p = &Bs[nxt][brow * BS_STRIDE + bc];
            p[0] = f2tf(b0.x); p[1] = f2tf(b0.y); p[2] = f2tf(b0.z); p[3] = f2tf(b0.w);
            p = &Bs[nxt][(brow + 8) * BS_STRIDE + bc];
            p[0] = f2tf(b1.x); p[1] = f2tf(b1.y); p[2] = f2tf(b1.z); p[3] = f2tf(b1.w);
            __syncthreads();
        }
    }

#pragma unroll
    for (int mt = 0; mt < 4; mt++) {
#pragma unroll
        for (int nt = 0; nt < 4; nt++) {
            int nloc = nb + warpN * 32 + nt * 8 + 2 * tg;
            int h = nloc >> 6, d = nloc & 63;
            float b0v = bias[nloc], b1v = bias[nloc + 1];
            int m0 = bm + warpM * 64 + mt * 16 + g;
            int m1 = m0 + 8;
            {
                int b = m0 >> 11, s = m0 & 2047;
                float2 o; o.x = c[mt][nt][0] + b0v; o.y = c[mt][nt][1] + b1v;
                *(float2*)&dst[(((size_t)b * HH + h) * SS + s) * DHH + d] = o;
            }
            {
                int b = m1 >> 11, s = m1 & 2047;
                float2 o; o.x = c[mt][nt][2] + b0v; o.y = c[mt][nt][3] + b1v;
                *(float2*)&dst[(((size_t)b * HH + h) * SS + s) * DHH + d] = o;
            }
        }
    }
}

// ---------------- REL GEMM (TF32), skewed fp16 store: g_rel[q][k] = Q[q]·Er[k+2047-q] ----------------
__global__ __launch_bounds__(256, 2) void k_rel()
{
    int bh = blockIdx.z;
    int r0 = blockIdx.x * 128, q0 = blockIdx.y * 128;
    if (q0 + r0 < 1793) return;

    __shared__ uint32_t As[2][128 * AS_STRIDE];
    __shared__ uint32_t Bs[2][16 * BS_STRIDE];

    const float* A = g_q + (size_t)bh * SS * DHH;

    int tid = threadIdx.x;
    int lane = tid & 31, wid = tid >> 5;
    int warpM = wid >> 2, warpN = wid & 3;
    int g = lane >> 2, tg = lane & 3;
    int arow = tid >> 2, ac = (tid & 3) * 4;
    int brow = tid >> 5, bc = (tid & 31) * 4;

    const float* Ap = A + (size_t)(q0 + arow) * DHH + ac;
    const float* Bp = g_erT + (size_t)brow * SS + r0 + bc;

    {
        float4 a0 = *(const float4*)Ap;
        float4 a1 = *(const float4*)(Ap + (size_t)64 * DHH);
        float4 b0 = *(const float4*)Bp;
        float4 b1 = *(const float4*)(Bp + (size_t)8 * SS);
        uint32_t* p;
        p = &As[0][arow * AS_STRIDE + ac];
        p[0] = f2tf(a0.x); p[1] = f2tf(a0.y); p[2] = f2tf(a0.z); p[3] = f2tf(a0.w);
        p = &As[0][(arow + 64) * AS_STRIDE + ac];
        p[0] = f2tf(a1.x); p[1] = f2tf(a1.y); p[2] = f2tf(a1.z); p[3] = f2tf(a1.w);
        p = &Bs[0][brow * BS_STRIDE + bc];
        p[0] = f2tf(b0.x); p[1] = f2tf(b0.y); p[2] = f2tf(b0.z); p[3] = f2tf(b0.w);
        p = &Bs[0][(brow + 8) * BS_STRIDE + bc];
        p[0] = f2tf(b1.x); p[1] = f2tf(b1.y); p[2] = f2tf(b1.z); p[3] = f2tf(b1.w);
    }
    __syncthreads();

    float c[4][4][4];
#pragma unroll
    for (int mt = 0; mt < 4; mt++)
#pragma unroll
        for (int nt = 0; nt < 4; nt++)
#pragma unroll
            for (int r = 0; r < 4; r++) c[mt][nt][r] = 0.f;

    for (int it = 0; it < 4; it++) {
        int cur = it & 1;
        float4 a0, a1, b0, b1;
        bool more = (it < 3);
        if (more) {
            const float* Ap2 = Ap + (it + 1) * 16;
            const float* Bp2 = Bp + (size_t)(it + 1) * 16 * SS;
            a0 = *(const float4*)Ap2;
            a1 = *(const float4*)(Ap2 + (size_t)64 * DHH);
            b0 = *(const float4*)Bp2;
            b1 = *(const float4*)(Bp2 + (size_t)8 * SS);
        }
#pragma unroll
        for (int ks2 = 0; ks2 < 2; ks2++) {
            int ks = ks2 * 8;
            uint32_t af[4][4], bf[4][2];
#pragma unroll
            for (int mt = 0; mt < 4; mt++) {
                int rb = warpM * 64 + mt * 16;
                af[mt][0] = As[cur][(rb + g)     * AS_STRIDE + ks + tg];
                af[mt][1] = As[cur][(rb + g + 8) * AS_STRIDE + ks + tg];
                af[mt][2] = As[cur][(rb + g)     * AS_STRIDE + ks + tg + 4];
                af[mt][3] = As[cur][(rb + g + 8) * AS_STRIDE + ks + tg + 4];
            }
#pragma unroll
            for (int nt = 0; nt < 4; nt++) {
                int cb = warpN * 32 + nt * 8;
                bf[nt][0] = Bs[cur][(ks + tg)     * BS_STRIDE + cb + g];
                bf[nt][1] = Bs[cur][(ks + tg + 4) * BS_STRIDE + cb + g];
            }
#pragma unroll
            for (int mt = 0; mt < 4; mt++)
#pragma unroll
                for (int nt = 0; nt < 4; nt++)
                    mma_tf32(c[mt][nt], af[mt], bf[nt]);
        }
        if (more) {
            int nxt = cur ^ 1;
            uint32_t* p;
            p = &As[nxt][arow * AS_STRIDE + ac];
            p[0] = f2tf(a0.x); p[1] = f2tf(a0.y); p[2] = f2tf(a0.z); p[3] = f2tf(a0.w);
            p = &As[nxt][(arow + 64) * AS_STRIDE + ac];
            p[0] = f2tf(a1.x); p[1] = f2tf(a1.y); p[2] = f2tf(a1.z); p[3] = f2tf(a1.w);
            p = &Bs[nxt][brow * BS_STRIDE + bc];
            p[0] = f2tf(b0.x); p[1] = f2tf(b0.y); p[2] = f2tf(b0.z); p[3] = f2tf(b0.w);
            p = &Bs[nxt][(brow + 8) * BS_STRIDE + bc];
            p[0] = f2tf(b1.x); p[1] = f2tf(b1.y); p[2] = f2tf(b1.z); p[3] = f2tf(b1.w);
            __syncthreads();
        }
    }

    // skewed epilogue: element (m, col) -> g_rel[m][col - (2047 - m)] when in causal band
    __half* C = g_rel + (size_t)bh * SS * SS;
#pragma unroll
    for (int mt = 0; mt < 4; mt++) {
#pragma unroll
        for (int nt = 0; nt < 4; nt++) {
            int col = r0 + warpN * 32 + nt * 8 + 2 * tg;
            int m0 = q0 + warpM * 64 + mt * 16 + g;
            int m1 = m0 + 8;
            int k0e = col - 2047 + m0;
            int k1e = col - 2047 + m1;
            if (k0e >= 0)     C[(size_t)m0 * SS + k0e]     = __float2half(c[mt][nt][0]);
            if (k0e + 1 >= 0) C[(size_t)m0 * SS + k0e + 1] = __float2half(c[mt][nt][1]);
            if (k1e >= 0)     C[(size_t)m1 * SS + k1e]     = __float2half(c[mt][nt][2]);
            if (k1e + 1 >= 0) C[(size_t)m1 * SS + k1e + 1] = __float2half(c[mt][nt][3]);
        }
    }
}

// ---------------- flash attention, TF32 tensor cores, 256 threads, 2 CTAs/SM ----------------
// 8 warps x 16 q-rows = 128 q per block; Bk = 64, single-buffered K/V, cross-CTA overlap.
// smem (u32): Ks[64*68] | Vs[64*72] | Ps[128*68] = 17664 u32 = 70656 B  (2 CTAs -> 141312 B/SM)
#define ATTN_SMEM_U32 (64*68 + 64*72 + 128*68)

__global__ __launch_bounds__(256, 2) void k_attn()
{
    extern __shared__ uint32_t smu[];
    uint32_t* Ks = smu;                 // [k][d] stride 68 (raw fp32 bits)
    uint32_t* Vs = Ks + 64 * 68;        // [k][d] stride 72 (raw fp32 bits)
    uint32_t* Ps = Vs + 64 * 72;        // [q][k] stride 68 (per-warp-private rows)

    int bh = blockIdx.y;
    int qt = (int)gridDim.x - 1 - (int)blockIdx.x;   // heavy tiles first
    int q0 = qt * 128;
    const float*  Q  = g_q + (size_t)bh * SS * DHH;
    const float*  Kp = g_k + (size_t)bh * SS * DHH;
    const float*  Vp = g_v + (size_t)bh * SS * DHH;
    const __half* R  = g_rel + (size_t)bh * SS * SS;

    int tid = threadIdx.x;
    int lane = tid & 31, wid = tid >> 5;   // wid 0..7
    int g = lane >> 2, tg = lane & 3;
    int qbase = q0 + wid * 16;
    int qlo = qbase + g, qhi = qlo + 8;

    // Q A-fragments in registers, loaded once, reused for every k-tile
    uint32_t qa[8][4];
#pragma unroll
    for (int ks = 0; ks < 8; ks++) {
        qa[ks][0] = f2tf(Q[(size_t)qlo * DHH + ks * 8 + tg]);
        qa[ks][1] = f2tf(Q[(size_t)qhi * DHH + ks * 8 + tg]);
        qa[ks][2] = f2tf(Q[(size_t)qlo * DHH + ks * 8 + tg + 4]);
        qa[ks][3] = f2tf(Q[(size_t)qhi * DHH + ks * 8 + tg + 4]);
    }

    float o[8][4];
#pragma unroll
    for (int nt = 0; nt < 8; nt++) { o[nt][0] = o[nt][1] = o[nt][2] = o[nt][3] = 0.f; }
    float mlo = -3.0e38f, mhi = -3.0e38f, llo = 0.f, lhi = 0.f;

    int prow_lo = (wid * 16 + g) * 68;
    int prow_hi = (wid * 16 + g + 8) * 68;

    int ntiles = 2 * qt + 2;   // k up to q0+127
    for (int t = 0; t < ntiles; t++) {
        int k0 = t * 64;
        __syncthreads();   // prior tile's reads of Ks/Vs done
        // stage K/V raw fp32 bits (TF32-truncated by the MMA), 4 x uint4 per thread
#pragma unroll
        for (int i = 0; i < 4; i++) {
            int idx = i * 256 + tid;               // 0..1023
            int ki = idx >> 4, c4 = (idx & 15) * 4;
            uint4 kv = *(const uint4*)&Kp[(size_t)(k0 + ki) * DHH + c4];
            *(uint4*)&Ks[ki * 68 + c4] = kv;
            uint4 vv = *(const uint4*)&Vp[(size_t)(k0 + ki) * DHH + c4];
            *(uint4*)&Vs[ki * 72 + c4] = vv;
        }
        __syncthreads();

        // warp-uniform causal bound (can be <= 0 for low warps at late tiles)
        int ntmax = min(8, ((qbase + 15 - k0) >> 3) + 1);
        if (ntmax > 0) {
            // ---- scores S = Q·K^T ----
            float s[8][4];
#pragma unroll
            for (int nt = 0; nt < 8; nt++) { s[nt][0] = s[nt][1] = s[nt][2] = s[nt][3] = 0.f; }
#pragma unroll
            for (int ks = 0; ks < 8; ks++) {
#pragma unroll
                for (int nt = 0; nt < 8; nt++) {
                    if (nt < ntmax) {
                        uint32_t bf[2];
                        bf[0] = Ks[(nt * 8 + g) * 68 + ks * 8 + tg];
                        bf[1] = Ks[(nt * 8 + g) * 68 + ks * 8 + tg + 4];
                        mma_tf32(s[nt], qa[ks], bf);
                    }
                }
            }

            // ---- + rel bias (fp16, aligned half2), scale, causal mask ----
            float tmlo = -3.0e38f, tmhi = -3.0e38f;
#pragma unroll
            for (int nt = 0; nt < 8; nt++) {
                if (nt < ntmax) {
                    int kk = k0 + nt * 8 + 2 * tg;
                    float2 rlo = __half22float2(*(const __half2*)&R[(size_t)qlo * SS + kk]);
                    float2 rhi = __half22float2(*(const __half2*)&R[(size_t)qhi * SS + kk]);
                    s[nt][0] = (kk     <= qlo) ? (s[nt][0] + rlo.x) * 0.125f : -1.0e30f;
                    s[nt][1] = (kk + 1 <= qlo) ? (s[nt][1] + rlo.y) * 0.125f : -1.0e30f;
                    s[nt][2] = (kk     <= qhi) ? (s[nt][2] + rhi.x) * 0.125f : -1.0e30f;
                    s[nt][3] = (kk + 1 <= qhi) ? (s[nt][3] + rhi.y) * 0.125f : -1.0e30f;
                    tmlo = fmaxf(tmlo, fmaxf(s[nt][0], s[nt][1]));
                    tmhi = fmaxf(tmhi, fmaxf(s[nt][2], s[nt][3]));
                }
            }

            // ---- online softmax (rows live in 4 tg lanes -> 2 shfls) ----
            tmlo = fmaxf(tmlo, __shfl_xor_sync(0xffffffffu, tmlo, 1));
            tmlo = fmaxf(tmlo, __shfl_xor_sync(0xffffffffu, tmlo, 2));
            tmhi = fmaxf(tmhi, __shfl_xor_sync(0xffffffffu, tmhi, 1));
            tmhi = fmaxf(tmhi, __shfl_xor_sync(0xffffffffu, tmhi, 2));
            float mnlo = fmaxf(mlo, tmlo), mnhi = fmaxf(mhi, tmhi);
            float clo = __expf(mlo - mnlo), chi = __expf(mhi - mnhi);
            mlo = mnlo; mhi = mnhi;

            float rslo = 0.f, rshi = 0.f;
#pragma unroll
            for (int nt = 0; nt < 8; nt++) {
                if (nt < ntmax) {
                    float p0 = __expf(s[nt][0] - mnlo);
                    float p1 = __expf(s[nt][1] - mnlo);
                    float p2 = __expf(s[nt][2] - mnhi);
                    float p3 = __expf(s[nt][3] - mnhi);
                    rslo += p0 + p1;
                    rshi += p2 + p3;
                    int col = nt * 8 + 2 * tg;
                    *(uint2*)&Ps[prow_lo + col] = make_uint2(f2tf(p0), f2tf(p1));
                    *(uint2*)&Ps[prow_hi + col] = make_uint2(f2tf(p2), f2tf(p3));
                }
            }
            rslo += __shfl_xor_sync(0xffffffffu, rslo, 1);
            rslo += __shfl_xor_sync(0xffffffffu, rslo, 2);
            rshi += __shfl_xor_sync(0xffffffffu, rshi, 1);
            rshi += __shfl_xor_sync(0xffffffffu, rshi, 2);
            llo = llo * clo + rslo;
            lhi = lhi * chi + rshi;
#pragma unroll
            for (int nt2 = 0; nt2 < 8; nt2++) {
                o[nt2][0] *= clo; o[nt2][1] *= clo;
                o[nt2][2] *= chi; o[nt2][3] *= chi;
            }

            __syncwarp();   // Ps rows are warp-private: warp-level ordering suffices

            // ---- O += P·V (skip k-groups where P == 0) ----
#pragma unroll
            for (int ks = 0; ks < 8; ks++) {
                if (ks < ntmax) {
                    uint32_t pa[4];
                    pa[0] = Ps[prow_lo + ks * 8 + tg];
                    pa[1] = Ps[prow_hi + ks * 8 + tg];
                    pa[2] = Ps[prow_lo + ks * 8 + tg + 4];
                    pa[3] = Ps[prow_hi + ks * 8 + tg + 4];
#pragma unroll
                    for (int nt2 = 0; nt2 < 8; nt2++) {
                        uint32_t bf[2];
                        bf[0] = Vs[(ks * 8 + tg)     * 72 + nt2 * 8 + g];
                        bf[1] = Vs[(ks * 8 + tg + 4) * 72 + nt2 * 8 + g];
                        mma_tf32(o[nt2], pa, bf);
                    }
                }
            }
        }
    }

    // ---- normalize + write head-interleaved [B,S,DA] ----
    float ilo = 1.0f / llo, ihi = 1.0f / lhi;
    int b = bh >> 4, h = bh & 15;
#pragma unroll
    for (int nt2 = 0; nt2 < 8; nt2++) {
        int d = nt2 * 8 + 2 * tg;
        float2 v0, v1;
        v0.x = o[nt2][0] * ilo; v0.y = o[nt2][1] * ilo;
        v1.x = o[nt2][2] * ihi; v1.y = o[nt2][3] * ihi;
        *(float2*)&g_att[((size_t)(b * SS + qlo)) * DMM + h * 64 + d] = v0;
        *(float2*)&g_att[((size_t)(b * SS + qhi)) * DMM + h * 64 + d] = v1;
    }
}

// ---------------- output projection, TF32 tensor-core GEMM ----------------
__global__ __launch_bounds__(256, 2) void k_out(
    const float* __restrict__ Wo, const float* __restrict__ bo, float* __restrict__ out)
{
    __shared__ uint32_t As[2][128 * AS_STRIDE];
    __shared__ uint32_t Bs[2][16 * BS_STRIDE];

    int bn = blockIdx.x * 128, bm = blockIdx.y * 128;

    int tid = threadIdx.x;
    int lane = tid & 31, wid = tid >> 5;
    int warpM = wid >> 2, warpN = wid & 3;
    int g = lane >> 2, tg = lane & 3;
    int arow = tid >> 2, ac = (tid & 3) * 4;
    int brow = tid >> 5, bc = (tid & 31) * 4;

    const float* Ap = g_att + (size_t)(bm + arow) * DMM + ac;
    const float* Bp = Wo + (size_t)brow * DMM + bn + bc;

    {
        float4 a0 = *(const float4*)Ap;
        float4 a1 = *(const float4*)(Ap + (size_t)64 * DMM);
        float4 b0 = *(const float4*)Bp;
        float4 b1 = *(const float4*)(Bp + (size_t)8 * DMM);
        uint32_t* p;
        p = &As[0][arow * AS_STRIDE + ac];
        p[0] = f2tf(a0.x); p[1] = f2tf(a0.y); p[2] = f2tf(a0.z); p[3] = f2tf(a0.w);
        p = &As[0][(arow + 64) * AS_STRIDE + ac];
        p[0] = f2tf(a1.x); p[1] = f2tf(a1.y); p[2] = f2tf(a1.z); p[3] = f2tf(a1.w);
        p = &Bs[0][brow * BS_STRIDE + bc];
        p[0] = f2tf(b0.x); p[1] = f2tf(b0.y); p[2] = f2tf(b0.z); p[3] = f2tf(b0.w);
        p = &Bs[0][(brow + 8) * BS_STRIDE + bc];
        p[0] = f2tf(b1.x); p[1] = f2tf(b1.y); p[2] = f2tf(b1.z); p[3] = f2tf(b1.w);
    }
    __syncthreads();

    float c[4][4][4];
#pragma unroll
    for (int mt = 0; mt < 4; mt++)
#pragma unroll
        for (int nt = 0; nt < 4; nt++)
#pragma unroll
            for (int r = 0; r < 4; r++) c[mt][nt][r] = 0.f;

    for (int it = 0; it < 64; it++) {
        int cur = it & 1;
        float4 a0, a1, b0, b1;
        bool more = (it < 63);
        if (more) {
            const float* Ap2 = Ap + (it + 1) * 16;
            const float* Bp2 = Bp + (size_t)(it + 1) * 16 * DMM;
            a0 = *(const float4*)Ap2;
            a1 = *(const float4*)(Ap2 + (size_t)64 * DMM);
            b0 = *(const float4*)Bp2;
            b1 = *(const float4*)(Bp2 + (size_t)8 * DMM);
        }
#pragma unroll
        for (int ks2 = 0; ks2 < 2; ks2++) {
            int ks = ks2 * 8;
            uint32_t af[4][4], bf[4][2];
#pragma unroll
            for (int mt = 0; mt < 4; mt++) {
                int rb = warpM * 64 + mt * 16;
                af[mt][0] = As[cur][(rb + g)     * AS_STRIDE + ks + tg];
                af[mt][1] = As[cur][(rb + g + 8) * AS_STRIDE + ks + tg];
                af[mt][2] = As[cur][(rb + g)     * AS_STRIDE + ks + tg + 4];
                af[mt][3] = As[cur][(rb + g + 8) * AS_STRIDE + ks + tg + 4];
            }
#pragma unroll
            for (int nt = 0; nt < 4; nt++) {
                int cb = warpN * 32 + nt * 8;
                bf[nt][0] = Bs[cur][(ks + tg)     * BS_STRIDE + cb + g];
                bf[nt][1] = Bs[cur][(ks + tg + 4) * BS_STRIDE + cb + g];
            }
#pragma unroll
            for (int mt = 0; mt < 4; mt++)
#pragma unroll
                for (int nt = 0; nt < 4; nt++)
                    mma_tf32(c[mt][nt], af[mt], bf[nt]);
        }
        if (more) {
            int nxt = cur ^ 1;
            uint32_t* p;
            p = &As[nxt][arow * AS_STRIDE + ac];
            p[0] = f2tf(a0.x); p[1] = f2tf(a0.y); p[2] = f2tf(a0.z); p[3] = f2tf(a0.w);
            p = &As[nxt][(arow + 64) * AS_STRIDE + ac];
            p[0] = f2tf(a1.x); p[1] = f2tf(a1.y); p[2] = f2tf(a1.z); p[3] = f2tf(a1.w);
            p = &Bs[nxt][brow * BS_STRIDE + bc];
            p[0] = f2tf(b0.x); p[1] = f2tf(b0.y); p[2] = f2tf(b0.z); p[3] = f2tf(b0.w);
            p = &Bs[nxt][(brow + 8) * BS_STRIDE + bc];
            p[0] = f2tf(b1.x); p[1] = f2tf(b1.y); p[2] = f2tf(b1.z); p[3] = f2tf(b1.w);
            __syncthreads();
        }
    }

#pragma unroll
    for (int mt = 0; mt < 4; mt++) {
#pragma unroll
        for (int nt = 0; nt < 4; nt++) {
            int n = bn + warpN * 32 + nt * 8 + 2 * tg;
            float b0v = bo[n], b1v = bo[n + 1];
            int m0 = bm + warpM * 64 + mt * 16 + g;
            float2 o0; o0.x = c[mt][nt][0] + b0v; o0.y = c[mt][nt][1] + b1v;
            float2 o1; o1.x = c[mt][nt][2] + b0v; o1.y = c[mt][nt][3] + b1v;
            *(float2*)&out[(size_t)m0 * DMM + n]       = o0;
            *(float2*)&out[(size_t)(m0 + 8) * DMM + n] = o1;
        }
    }
}

// ---------------- launch ----------------
extern "C" void kernel_launch(void* const* d_in, const int* in_sizes, int n_in,
                              void* d_out, int out_size)
{
    const float* x  = (const float*)d_in[0];
    const float* Wq = (const float*)d_in[1];
    const float* bq = (const float*)d_in[2];
    const float* Wk = (const float*)d_in[3];
    const float* bk = (const float*)d_in[4];
    const float* Wv = (const float*)d_in[5];
    const float* bv = (const float*)d_in[6];
    const float* Wo = (const float*)d_in[7];
    const float* bo = (const float*)d_in[8];
    const float* Er = (const float*)d_in[9];
    float* out = (float*)d_out;

    cudaFuncSetAttribute((const void*)k_attn,
                         cudaFuncAttributeMaxDynamicSharedMemorySize,
                         ATTN_SMEM_U32 * (int)sizeof(uint32_t));

    k_transpose_er<<<512, 256>>>(Er);
    k_qkv<<<dim3(24, 32), 256>>>(x, Wq, Wk, Wv, bq, bk, bv);
    k_rel<<<dim3(16, 16, 32), 256>>>();
    k_attn<<<dim3(16, 32), 256, ATTN_SMEM_U32 * sizeof(uint32_t)>>>();
    k_out<<<dim3(8, 32), 256>>>(Wo, bo, out);
}